// round 1
// baseline (speedup 1.0000x reference)
#include <cuda_runtime.h>
#include <math.h>

#define N_TOK 2048
#define DIMX  1024
#define HEADS 16
#define DHEAD 64
#define INNER 1024
#define ALPHA_C 0.45f
#define SCALE_C 0.125f   // 64^-0.5

// ---------------- scratch (single device global, ~336MB) ----------------
// offsets in floats
#define OFF_XN   ((size_t)0)                              // 2048*1024
#define OFF_C1   (OFF_XN  + (size_t)N_TOK*DIMX)           // 2048*1024
#define OFF_C2   (OFF_C1  + (size_t)N_TOK*INNER)          // 2048*2048
#define OFF_Q    (OFF_C2  + (size_t)N_TOK*2*INNER)        // 16*2048*64
#define OFF_K    (OFF_Q   + (size_t)HEADS*N_TOK*DHEAD)
#define OFF_V    (OFF_K   + (size_t)HEADS*N_TOK*DHEAD)
#define OFF_DOTS (OFF_V   + (size_t)HEADS*N_TOK*DHEAD)    // 16*2048*2048
#define OFF_M    (OFF_DOTS+ (size_t)HEADS*N_TOK*N_TOK)    // 16*2048
#define OFF_L    (OFF_M   + (size_t)HEADS*N_TOK)
#define OFF_AO   (OFF_L   + (size_t)HEADS*N_TOK)          // 2048*1024
#define SCRATCH_FLOATS (OFF_AO + (size_t)N_TOK*INNER)

__device__ float g_scratch[SCRATCH_FLOATS];

// ---------------- layernorm ----------------
__global__ void ln_kernel(const float* __restrict__ x,
                          const float* __restrict__ gam,
                          const float* __restrict__ bet,
                          float* __restrict__ out)
{
    int row = blockIdx.x;
    const float* xr = x + (size_t)row * DIMX;
    float s = 0.f, s2 = 0.f;
    for (int c = threadIdx.x; c < DIMX; c += blockDim.x) {
        float v = xr[c];
        s += v; s2 += v * v;
    }
    __shared__ float red[64];
    for (int o = 16; o > 0; o >>= 1) {
        s  += __shfl_xor_sync(0xffffffffu, s,  o);
        s2 += __shfl_xor_sync(0xffffffffu, s2, o);
    }
    int warp = threadIdx.x >> 5, lane = threadIdx.x & 31;
    int nwarp = blockDim.x >> 5;
    if (lane == 0) { red[warp] = s; red[warp + 32] = s2; }
    __syncthreads();
    if (warp == 0) {
        s  = (lane < nwarp) ? red[lane] : 0.f;
        s2 = (lane < nwarp) ? red[lane + 32] : 0.f;
        for (int o = 16; o > 0; o >>= 1) {
            s  += __shfl_xor_sync(0xffffffffu, s,  o);
            s2 += __shfl_xor_sync(0xffffffffu, s2, o);
        }
        if (lane == 0) { red[0] = s; red[1] = s2; }
    }
    __syncthreads();
    float mean = red[0] * (1.f / DIMX);
    float var  = red[1] * (1.f / DIMX) - mean * mean;
    float inv  = rsqrtf(var + 1e-5f);
    float* o = out + (size_t)row * DIMX;
    for (int c = threadIdx.x; c < DIMX; c += blockDim.x)
        o[c] = (xr[c] - mean) * inv * gam[c] + bet[c];
}

// ---------------- generic tiled SGEMM (NN / NT) ----------------
// C[M,Nc] = alpha * A @ opB(B) (+ bias), batched via blockIdx.z
// NN: B is (K x Nc) row-major.  NT: B is (Nc x K) row-major (C = A B^T).
template<bool TRANSB>
__global__ void sgemm_kernel(const float* __restrict__ A,
                             const float* __restrict__ B,
                             float* __restrict__ C,
                             int M, int Nc, int K,
                             int lda, int ldb, int ldc,
                             long long strA, long long strB, long long strC,
                             float alpha, const float* __restrict__ bias)
{
    const int BM = 128, BN = 128, BK = 16;
    __shared__ float As[BK][BM + 4];
    __shared__ float Bs[BK][BN + 4];

    A += (size_t)blockIdx.z * strA;
    B += (size_t)blockIdx.z * strB;
    C += (size_t)blockIdx.z * strC;

    int bm = blockIdx.y * BM, bn = blockIdx.x * BN;
    int tid = threadIdx.x;
    int tx = tid & 15, ty = tid >> 4;

    float acc[8][8];
#pragma unroll
    for (int i = 0; i < 8; i++)
#pragma unroll
        for (int j = 0; j < 8; j++) acc[i][j] = 0.f;

    for (int k0 = 0; k0 < K; k0 += BK) {
        // A tile: rows bm..bm+127, cols k0..k0+15 -> As[col][row]
#pragma unroll
        for (int i = 0; i < 8; i++) {
            int e = tid + i * 256;
            int col = e & (BK - 1);
            int row = e >> 4;
            float v = 0.f;
            if (bm + row < M && k0 + col < K)
                v = A[(size_t)(bm + row) * lda + (k0 + col)];
            As[col][row] = v;
        }
        // B tile
#pragma unroll
        for (int i = 0; i < 8; i++) {
            int e = tid + i * 256;
            if (!TRANSB) {
                int col  = e & (BN - 1);
                int krow = e >> 7;
                float v = 0.f;
                if (k0 + krow < K && bn + col < Nc)
                    v = B[(size_t)(k0 + krow) * ldb + (bn + col)];
                Bs[krow][col] = v;
            } else {
                int kk   = e & (BK - 1);
                int nrow = e >> 4;
                float v = 0.f;
                if (bn + nrow < Nc && k0 + kk < K)
                    v = B[(size_t)(bn + nrow) * ldb + (k0 + kk)];
                Bs[kk][nrow] = v;
            }
        }
        __syncthreads();
#pragma unroll
        for (int kk = 0; kk < BK; kk++) {
            float ra[8], rb[8];
#pragma unroll
            for (int i = 0; i < 8; i++) ra[i] = As[kk][ty * 8 + i];
#pragma unroll
            for (int j = 0; j < 8; j++) rb[j] = Bs[kk][tx * 8 + j];
#pragma unroll
            for (int i = 0; i < 8; i++)
#pragma unroll
                for (int j = 0; j < 8; j++)
                    acc[i][j] += ra[i] * rb[j];
        }
        __syncthreads();
    }

#pragma unroll
    for (int i = 0; i < 8; i++) {
        int r = bm + ty * 8 + i;
        if (r >= M) continue;
#pragma unroll
        for (int j = 0; j < 8; j++) {
            int c = bn + tx * 8 + j;
            if (c >= Nc) continue;
            float v = acc[i][j] * alpha;
            if (bias) v += bias[c];
            C[(size_t)r * ldc + c] = v;
        }
    }
}

// ---------------- remap (i, h*64+d) -> [h][i][d] ----------------
__global__ void remap_qkv(const float* __restrict__ c1,
                          const float* __restrict__ c2,
                          float* __restrict__ q,
                          float* __restrict__ k,
                          float* __restrict__ v)
{
    int idx = blockIdx.x * blockDim.x + threadIdx.x;
    if (idx >= N_TOK * INNER) return;
    int i = idx / INNER, col = idx % INNER;
    int h = col / DHEAD, d = col % DHEAD;
    size_t dst = ((size_t)h * N_TOK + i) * DHEAD + d;
    q[dst] = c1[idx];
    k[dst] = c2[(size_t)i * 2 * INNER + col];
    v[dst] = c2[(size_t)i * 2 * INNER + INNER + col];
}

// ---------------- blend + mix_pre + online softmax stats ----------------
// one block per row i. dots[h][i][j] holds raw (already scaled); overwritten
// in place with mix_pre-mixed dots. blended written to d_out region.
__global__ void blend_kernel(float* __restrict__ dots,
                             const float* __restrict__ hin,
                             const float* __restrict__ mix_pre,
                             float* __restrict__ blended_out,
                             float* __restrict__ gm,
                             float* __restrict__ gl)
{
    __shared__ float smix[HEADS * HEADS];
    int i = blockIdx.x;
    int tid = threadIdx.x;
    if (tid < HEADS * HEADS) smix[tid] = mix_pre[tid];
    __syncthreads();

    const size_t sH = (size_t)N_TOK * N_TOK;
    const size_t rowOff = (size_t)i * N_TOK;

    float m[HEADS], l[HEADS];
#pragma unroll
    for (int g = 0; g < HEADS; g++) { m[g] = -INFINITY; l[g] = 0.f; }

    for (int j = tid; j < N_TOK; j += 256) {
        float bl[HEADS];
#pragma unroll
        for (int h = 0; h < HEADS; h++) {
            float raw = dots[h * sH + rowOff + j];
            float hv  = hin [h * sH + rowOff + j];
            bl[h] = ALPHA_C * raw + (1.f - ALPHA_C) * hv;
            blended_out[h * sH + rowOff + j] = bl[h];
        }
#pragma unroll
        for (int g = 0; g < HEADS; g++) {
            float d = 0.f;
#pragma unroll
            for (int h = 0; h < HEADS; h++) d += bl[h] * smix[h * HEADS + g];
            dots[g * sH + rowOff + j] = d;
            float om = m[g];
            float nm = fmaxf(om, d);
            l[g] = l[g] * expf(om - nm) + expf(d - nm);
            m[g] = nm;
        }
    }

    __shared__ float rm[256], rl[256];
    for (int g = 0; g < HEADS; g++) {
        rm[tid] = m[g]; rl[tid] = l[g];
        __syncthreads();
        for (int s = 128; s > 0; s >>= 1) {
            if (tid < s) {
                float m1 = rm[tid], m2 = rm[tid + s];
                float l1 = rl[tid], l2 = rl[tid + s];
                float mm = fmaxf(m1, m2);
                rm[tid] = mm;
                rl[tid] = l1 * expf(m1 - mm) + l2 * expf(m2 - mm);
            }
            __syncthreads();
        }
        if (tid == 0) { gm[g * N_TOK + i] = rm[0]; gl[g * N_TOK + i] = rl[0]; }
        __syncthreads();
    }
}

// ---------------- normalize + mix_post (in place) ----------------
__global__ void mixpost_kernel(float* __restrict__ dots,
                               const float* __restrict__ mix_post,
                               const float* __restrict__ gm,
                               const float* __restrict__ gl)
{
    __shared__ float smix[HEADS * HEADS];
    int tid = threadIdx.x;
    if (tid < HEADS * HEADS) smix[tid] = mix_post[tid];
    __syncthreads();

    int i = blockIdx.y;
    int j = blockIdx.x * blockDim.x + tid;
    const size_t sH = (size_t)N_TOK * N_TOK;
    const size_t rowOff = (size_t)i * N_TOK;

    float p[HEADS];
#pragma unroll
    for (int h = 0; h < HEADS; h++) {
        float d = dots[h * sH + rowOff + j];
        float linv = 1.0f / gl[h * N_TOK + i];
        p[h] = expf(d - gm[h * N_TOK + i]) * linv;
    }
#pragma unroll
    for (int g = 0; g < HEADS; g++) {
        float a = 0.f;
#pragma unroll
        for (int h = 0; h < HEADS; h++) a += p[h] * smix[h * HEADS + g];
        dots[g * sH + rowOff + j] = a;
    }
}

// ---------------- launch ----------------
extern "C" void kernel_launch(void* const* d_in, const int* in_sizes, int n_in,
                              void* d_out, int out_size)
{
    const float* x        = (const float*)d_in[0];
    const float* h_in     = (const float*)d_in[1];
    const float* ln_g     = (const float*)d_in[2];
    const float* ln_b     = (const float*)d_in[3];
    const float* Wq       = (const float*)d_in[4];
    const float* Wkv      = (const float*)d_in[5];
    const float* mix_pre  = (const float*)d_in[6];
    const float* mix_post = (const float*)d_in[7];
    const float* Wout     = (const float*)d_in[8];
    const float* bout     = (const float*)d_in[9];

    float* out = (float*)d_out;
    float* blended_out = out + (size_t)N_TOK * DIMX;

    float* S = nullptr;
    cudaGetSymbolAddress((void**)&S, g_scratch);
    float* xn   = S + OFF_XN;
    float* c1   = S + OFF_C1;
    float* c2   = S + OFF_C2;
    float* q    = S + OFF_Q;
    float* k    = S + OFF_K;
    float* v    = S + OFF_V;
    float* dots = S + OFF_DOTS;
    float* gm   = S + OFF_M;
    float* gl   = S + OFF_L;
    float* ao   = S + OFF_AO;

    // 1. layernorm
    ln_kernel<<<N_TOK, 256>>>(x, ln_g, ln_b, xn);

    // 2. q = xn@Wq, kv = xn@Wkv
    {
        dim3 g1((INNER + 127) / 128, (N_TOK + 127) / 128, 1);
        sgemm_kernel<false><<<g1, 256>>>(xn, Wq, c1, N_TOK, INNER, DIMX,
                                         DIMX, INNER, INNER, 0, 0, 0, 1.f, nullptr);
        dim3 g2((2 * INNER + 127) / 128, (N_TOK + 127) / 128, 1);
        sgemm_kernel<false><<<g2, 256>>>(xn, Wkv, c2, N_TOK, 2 * INNER, DIMX,
                                         DIMX, 2 * INNER, 2 * INNER, 0, 0, 0, 1.f, nullptr);
    }

    // 3. remap to per-head layout
    remap_qkv<<<(N_TOK * INNER + 255) / 256, 256>>>(c1, c2, q, k, v);

    // 4. raw = scale * q @ k^T  (batched over heads)
    {
        dim3 g((N_TOK + 127) / 128, (N_TOK + 127) / 128, HEADS);
        sgemm_kernel<true><<<g, 256>>>(q, k, dots, N_TOK, N_TOK, DHEAD,
                                       DHEAD, DHEAD, N_TOK,
                                       (long long)N_TOK * DHEAD,
                                       (long long)N_TOK * DHEAD,
                                       (long long)N_TOK * N_TOK,
                                       SCALE_C, nullptr);
    }

    // 5. blended (to output) + mix_pre (in place) + softmax stats
    blend_kernel<<<N_TOK, 256>>>(dots, h_in, mix_pre, blended_out, gm, gl);

    // 6. normalize + mix_post (in place)
    {
        dim3 g(N_TOK / 256, N_TOK, 1);
        mixpost_kernel<<<g, 256>>>(dots, mix_post, gm, gl);
    }

    // 7. out_heads = attn @ v  -> ao[i][g*64+d]  (batched over heads)
    {
        dim3 g((DHEAD + 127) / 128, (N_TOK + 127) / 128, HEADS);
        sgemm_kernel<false><<<g, 256>>>(dots, v, ao, N_TOK, DHEAD, N_TOK,
                                        N_TOK, DHEAD, INNER,
                                        (long long)N_TOK * N_TOK,
                                        (long long)N_TOK * DHEAD,
                                        (long long)DHEAD,
                                        1.f, nullptr);
    }

    // 8. out = ao @ Wout + bout
    {
        dim3 g((DIMX + 127) / 128, (N_TOK + 127) / 128, 1);
        sgemm_kernel<false><<<g, 256>>>(ao, Wout, out, N_TOK, DIMX, INNER,
                                        INNER, DIMX, DIMX, 0, 0, 0, 1.f, bout);
    }
    (void)in_sizes; (void)n_in; (void)out_size;
}

// round 2
// speedup vs baseline: 1.9543x; 1.9543x over previous
#include <cuda_runtime.h>
#include <math.h>

#define N_TOK 2048
#define DIMX  1024
#define HEADS 16
#define DHEAD 64
#define INNER 1024
#define ALPHA_C 0.45f
#define SCALE_C 0.125f   // 64^-0.5

// ---------------- scratch (single device global) ----------------
#define OFF_XN   ((size_t)0)                              // 2048*1024
#define OFF_C1   (OFF_XN  + (size_t)N_TOK*DIMX)           // 2048*1024
#define OFF_C2   (OFF_C1  + (size_t)N_TOK*INNER)          // 2048*2048
#define OFF_Q    (OFF_C2  + (size_t)N_TOK*2*INNER)
#define OFF_K    (OFF_Q   + (size_t)HEADS*N_TOK*DHEAD)
#define OFF_V    (OFF_K   + (size_t)HEADS*N_TOK*DHEAD)
#define OFF_DOTS (OFF_V   + (size_t)HEADS*N_TOK*DHEAD)    // 16*2048*2048 (interleaved [i][h][j])
#define OFF_M    (OFF_DOTS+ (size_t)HEADS*N_TOK*N_TOK)
#define OFF_L    (OFF_M   + (size_t)HEADS*N_TOK)
#define OFF_AO   (OFF_L   + (size_t)HEADS*N_TOK)          // 2048*1024
#define SCRATCH_FLOATS (OFF_AO + (size_t)N_TOK*INNER)

__device__ float g_scratch[SCRATCH_FLOATS];

// ---------------- f32x2 helpers ----------------
__device__ __forceinline__ unsigned long long dup2(float v) {
    unsigned long long r;
    asm("mov.b64 %0, {%1, %1};" : "=l"(r) : "f"(v));
    return r;
}
__device__ __forceinline__ void ffma2(unsigned long long& d,
                                      unsigned long long a,
                                      unsigned long long b) {
    asm("fma.rn.f32x2 %0, %1, %2, %3;" : "=l"(d) : "l"(a), "l"(b), "l"(d));
}
__device__ __forceinline__ void unpack2(unsigned long long p, float& x, float& y) {
    asm("mov.b64 {%0, %1}, %2;" : "=f"(x), "=f"(y) : "l"(p));
}

// ---------------- layernorm ----------------
__global__ void ln_kernel(const float* __restrict__ x,
                          const float* __restrict__ gam,
                          const float* __restrict__ bet,
                          float* __restrict__ out)
{
    int row = blockIdx.x;
    const float* xr = x + (size_t)row * DIMX;
    float s = 0.f, s2 = 0.f;
    for (int c = threadIdx.x; c < DIMX; c += blockDim.x) {
        float v = xr[c];
        s += v; s2 += v * v;
    }
    __shared__ float red[64];
    for (int o = 16; o > 0; o >>= 1) {
        s  += __shfl_xor_sync(0xffffffffu, s,  o);
        s2 += __shfl_xor_sync(0xffffffffu, s2, o);
    }
    int warp = threadIdx.x >> 5, lane = threadIdx.x & 31;
    int nwarp = blockDim.x >> 5;
    if (lane == 0) { red[warp] = s; red[warp + 32] = s2; }
    __syncthreads();
    if (warp == 0) {
        s  = (lane < nwarp) ? red[lane] : 0.f;
        s2 = (lane < nwarp) ? red[lane + 32] : 0.f;
        for (int o = 16; o > 0; o >>= 1) {
            s  += __shfl_xor_sync(0xffffffffu, s,  o);
            s2 += __shfl_xor_sync(0xffffffffu, s2, o);
        }
        if (lane == 0) { red[0] = s; red[1] = s2; }
    }
    __syncthreads();
    float mean = red[0] * (1.f / DIMX);
    float var  = red[1] * (1.f / DIMX) - mean * mean;
    float inv  = rsqrtf(var + 1e-5f);
    float* o = out + (size_t)row * DIMX;
    for (int c = threadIdx.x; c < DIMX; c += blockDim.x)
        o[c] = (xr[c] - mean) * inv * gam[c] + bet[c];
}

// ---------------- FFMA2 double-buffered SGEMM ----------------
// BM=128, BK=16, BN template (128 or 64). 256 threads, 8 rows x (BN/16) cols
// per thread, columns grouped as pairs at (tx*2 + j*32).
// A is duplicated into (a,a) ULL pairs in smem so the inner loop is
// LDS.64 + fma.rn.f32x2 only. All dims must divide tile sizes exactly.
template<int BN, bool TRANSB>
__global__ void __launch_bounds__(256)
gemm2_kernel(const float* __restrict__ A, const float* __restrict__ B,
             float* __restrict__ C, int K, int lda, int ldb, int ldc,
             long long strA, long long strB, long long strC,
             float alpha, const float* __restrict__ bias)
{
    constexpr int BM = 128, BK = 16;
    constexpr int JP = BN / 32;          // column-pair groups per thread
    constexpr int BSTG = BN / 64;        // B float4s per thread per tile

    __shared__ unsigned long long As2[2][BK][BM];   // (a,a) pairs, row-skewed
    __shared__ float Bs[2][BK][BN];                 // col-skewed

    A += (size_t)blockIdx.z * strA;
    B += (size_t)blockIdx.z * strB;
    C += (size_t)blockIdx.z * strC;

    const int bm = blockIdx.y * BM, bn = blockIdx.x * BN;
    const int tid = threadIdx.x;
    const int tx = tid & 15, ty = tid >> 4;

    unsigned long long acc[8][JP];
#pragma unroll
    for (int i = 0; i < 8; i++)
#pragma unroll
        for (int j = 0; j < JP; j++) acc[i][j] = 0ull;

    const int KT = K / BK;

    float4 aS[2];
    float4 bS[BSTG];

    // ---- fetch tile kt into stage regs ----
    auto fetchA = [&](int kt) {
        int k0 = kt * BK;
#pragma unroll
        for (int t = 0; t < 2; t++) {
            int f = tid + t * 256;
            int r = f >> 2, c4 = (f & 3) * 4;
            aS[t] = *(const float4*)&A[(size_t)(bm + r) * lda + k0 + c4];
        }
    };
    auto fetchB = [&](int kt) {
        int k0 = kt * BK;
        if (!TRANSB) {
#pragma unroll
            for (int t = 0; t < BSTG; t++) {
                int f = tid + t * 256;
                int krow = f / (BN / 4), col4 = (f % (BN / 4)) * 4;
                bS[t] = *(const float4*)&B[(size_t)(k0 + krow) * ldb + bn + col4];
            }
        } else {
#pragma unroll
            for (int t = 0; t < BSTG; t++) {
                int f = tid + t * 256;
                int n = f >> 2, kc4 = (f & 3) * 4;
                bS[t] = *(const float4*)&B[(size_t)(bn + n) * ldb + k0 + kc4];
            }
        }
    };
    // ---- store stage regs into smem buffer b ----
    auto storeA = [&](int b) {
#pragma unroll
        for (int t = 0; t < 2; t++) {
            int f = tid + t * 256;
            int r = f >> 2, c4 = (f & 3) * 4;
            float vv[4] = {aS[t].x, aS[t].y, aS[t].z, aS[t].w};
#pragma unroll
            for (int c = 0; c < 4; c++)
                As2[b][c4 + c][(r + 2 * (c4 + c)) & (BM - 1)] = dup2(vv[c]);
        }
    };
    auto storeB = [&](int b) {
        if (!TRANSB) {
#pragma unroll
            for (int t = 0; t < BSTG; t++) {
                int f = tid + t * 256;
                int krow = f / (BN / 4), col4 = (f % (BN / 4)) * 4;
                int scol = (col4 + 4 * krow) & (BN - 1);
                *(float4*)&Bs[b][krow][scol] = bS[t];
            }
        } else {
#pragma unroll
            for (int t = 0; t < BSTG; t++) {
                int f = tid + t * 256;
                int n = f >> 2, kc4 = (f & 3) * 4;
                float vv[4] = {bS[t].x, bS[t].y, bS[t].z, bS[t].w};
#pragma unroll
                for (int c = 0; c < 4; c++) {
                    int kk = kc4 + c;
                    Bs[b][kk][(n + 4 * kk) & (BN - 1)] = vv[c];
                }
            }
        }
    };

    fetchA(0); fetchB(0);
    storeA(0); storeB(0);
    __syncthreads();

    for (int kt = 0; kt < KT; ++kt) {
        int cur = kt & 1;
        if (kt + 1 < KT) { fetchA(kt + 1); fetchB(kt + 1); }

#pragma unroll
        for (int kk = 0; kk < BK; kk++) {
            unsigned long long ra[8];
#pragma unroll
            for (int i = 0; i < 8; i++)
                ra[i] = As2[cur][kk][(ty * 8 + i + 2 * kk) & (BM - 1)];
            unsigned long long rb[JP];
#pragma unroll
            for (int j = 0; j < JP; j++) {
                int idx = (tx * 2 + j * 32 + 4 * kk) & (BN - 1);
                rb[j] = *(const unsigned long long*)&Bs[cur][kk][idx];
            }
#pragma unroll
            for (int i = 0; i < 8; i++)
#pragma unroll
                for (int j = 0; j < JP; j++)
                    ffma2(acc[i][j], ra[i], rb[j]);
        }

        if (kt + 1 < KT) {
            storeA(cur ^ 1); storeB(cur ^ 1);
            __syncthreads();
        }
    }

    // ---- epilogue ----
#pragma unroll
    for (int i = 0; i < 8; i++) {
        size_t row = (size_t)(bm + ty * 8 + i);
#pragma unroll
        for (int j = 0; j < JP; j++) {
            int col = bn + tx * 2 + j * 32;
            float x, y;
            unpack2(acc[i][j], x, y);
            x *= alpha; y *= alpha;
            if (bias) { x += bias[col]; y += bias[col + 1]; }
            float2 o = make_float2(x, y);
            *(float2*)&C[row * (size_t)ldc + col] = o;
        }
    }
}

// ---------------- remap (i, h*64+d) -> [h][i][d] ----------------
__global__ void remap_qkv(const float* __restrict__ c1,
                          const float* __restrict__ c2,
                          float* __restrict__ q,
                          float* __restrict__ k,
                          float* __restrict__ v)
{
    int idx = blockIdx.x * blockDim.x + threadIdx.x;
    if (idx >= N_TOK * INNER) return;
    int i = idx / INNER, col = idx % INNER;
    int h = col / DHEAD, d = col % DHEAD;
    size_t dst = ((size_t)h * N_TOK + i) * DHEAD + d;
    q[dst] = c1[idx];
    k[dst] = c2[(size_t)i * 2 * INNER + col];
    v[dst] = c2[(size_t)i * 2 * INNER + INNER + col];
}

// ---------------- blend + mix_pre + online softmax stats ----------------
// dots2 layout: [i][h][j] (row i = 16 contiguous planes of 2048).
// blended (output) layout: [h][i][j] per reference.
__global__ void __launch_bounds__(256)
blend_kernel(float* __restrict__ dots2, const float* __restrict__ hin,
             const float* __restrict__ mp, float* __restrict__ blended,
             float* __restrict__ gm, float* __restrict__ gl)
{
    __shared__ float smix[HEADS * HEADS];
    __shared__ float redm[8][HEADS], redl[8][HEADS];
    const int i = blockIdx.x, tid = threadIdx.x;
    smix[tid & 255] = mp[tid & 255];
    __syncthreads();

    const size_t rbase = (size_t)i * (HEADS * N_TOK);
    const size_t hbase = (size_t)i * N_TOK;
    const size_t sH = (size_t)N_TOK * N_TOK;

    float m[HEADS], l[HEADS];
#pragma unroll
    for (int g = 0; g < HEADS; g++) { m[g] = -INFINITY; l[g] = 0.f; }

    for (int j = tid * 4; j < N_TOK; j += 1024) {
        float4 bl4[HEADS];
#pragma unroll
        for (int h = 0; h < HEADS; h++) {
            float4 r  = *(const float4*)&dots2[rbase + h * N_TOK + j];
            float4 hv = *(const float4*)&hin[(size_t)h * sH + hbase + j];
            float4 b;
            b.x = ALPHA_C * r.x + (1.f - ALPHA_C) * hv.x;
            b.y = ALPHA_C * r.y + (1.f - ALPHA_C) * hv.y;
            b.z = ALPHA_C * r.z + (1.f - ALPHA_C) * hv.z;
            b.w = ALPHA_C * r.w + (1.f - ALPHA_C) * hv.w;
            *(float4*)&blended[(size_t)h * sH + hbase + j] = b;
            bl4[h] = b;
        }
#pragma unroll
        for (int g = 0; g < HEADS; g++) {
            float4 d = make_float4(0.f, 0.f, 0.f, 0.f);
#pragma unroll
            for (int h = 0; h < HEADS; h++) {
                float w = smix[h * HEADS + g];
                d.x += bl4[h].x * w; d.y += bl4[h].y * w;
                d.z += bl4[h].z * w; d.w += bl4[h].w * w;
            }
            *(float4*)&dots2[rbase + g * N_TOK + j] = d;
            float mx = fmaxf(fmaxf(d.x, d.y), fmaxf(d.z, d.w));
            float nm = fmaxf(m[g], mx);
            l[g] = l[g] * __expf(m[g] - nm)
                 + __expf(d.x - nm) + __expf(d.y - nm)
                 + __expf(d.z - nm) + __expf(d.w - nm);
            m[g] = nm;
        }
    }

    // warp reduction
#pragma unroll
    for (int g = 0; g < HEADS; g++) {
        for (int o = 16; o > 0; o >>= 1) {
            float m2 = __shfl_xor_sync(0xffffffffu, m[g], o);
            float l2 = __shfl_xor_sync(0xffffffffu, l[g], o);
            float nm = fmaxf(m[g], m2);
            l[g] = l[g] * __expf(m[g] - nm) + l2 * __expf(m2 - nm);
            m[g] = nm;
        }
    }
    int warp = tid >> 5, lane = tid & 31;
    if (lane == 0) {
#pragma unroll
        for (int g = 0; g < HEADS; g++) { redm[warp][g] = m[g]; redl[warp][g] = l[g]; }
    }
    __syncthreads();
    if (tid < HEADS) {
        int g = tid;
        float M = redm[0][g], L = redl[0][g];
#pragma unroll
        for (int w = 1; w < 8; w++) {
            float m2 = redm[w][g], l2 = redl[w][g];
            float nm = fmaxf(M, m2);
            L = L * __expf(M - nm) + l2 * __expf(m2 - nm);
            M = nm;
        }
        gm[g * N_TOK + i] = M;
        gl[g * N_TOK + i] = L;
    }
}

// ---------------- normalize + mix_post (in place on dots2) ----------------
__global__ void __launch_bounds__(256)
mixpost_kernel(float* __restrict__ dots2, const float* __restrict__ mp,
               const float* __restrict__ gm, const float* __restrict__ gl)
{
    __shared__ float smix[HEADS * HEADS];
    const int tid = threadIdx.x;
    smix[tid & 255] = mp[tid & 255];
    __syncthreads();

    const int i = blockIdx.y;
    const int j = (blockIdx.x * 256 + tid) * 4;
    const size_t rbase = (size_t)i * (HEADS * N_TOK);

    float4 p4[HEADS];
#pragma unroll
    for (int h = 0; h < HEADS; h++) {
        float mh = gm[h * N_TOK + i];
        float li = 1.0f / gl[h * N_TOK + i];
        float4 d = *(const float4*)&dots2[rbase + h * N_TOK + j];
        p4[h].x = __expf(d.x - mh) * li;
        p4[h].y = __expf(d.y - mh) * li;
        p4[h].z = __expf(d.z - mh) * li;
        p4[h].w = __expf(d.w - mh) * li;
    }
#pragma unroll
    for (int g = 0; g < HEADS; g++) {
        float4 a = make_float4(0.f, 0.f, 0.f, 0.f);
#pragma unroll
        for (int h = 0; h < HEADS; h++) {
            float w = smix[h * HEADS + g];
            a.x += p4[h].x * w; a.y += p4[h].y * w;
            a.z += p4[h].z * w; a.w += p4[h].w * w;
        }
        *(float4*)&dots2[rbase + g * N_TOK + j] = a;
    }
}

// ---------------- launch ----------------
extern "C" void kernel_launch(void* const* d_in, const int* in_sizes, int n_in,
                              void* d_out, int out_size)
{
    const float* x        = (const float*)d_in[0];
    const float* h_in     = (const float*)d_in[1];
    const float* ln_g     = (const float*)d_in[2];
    const float* ln_b     = (const float*)d_in[3];
    const float* Wq       = (const float*)d_in[4];
    const float* Wkv      = (const float*)d_in[5];
    const float* mix_pre  = (const float*)d_in[6];
    const float* mix_post = (const float*)d_in[7];
    const float* Wout     = (const float*)d_in[8];
    const float* bout     = (const float*)d_in[9];

    float* out = (float*)d_out;
    float* blended_out = out + (size_t)N_TOK * DIMX;

    float* S = nullptr;
    cudaGetSymbolAddress((void**)&S, g_scratch);
    float* xn    = S + OFF_XN;
    float* c1    = S + OFF_C1;
    float* c2    = S + OFF_C2;
    float* q     = S + OFF_Q;
    float* k     = S + OFF_K;
    float* v     = S + OFF_V;
    float* dots2 = S + OFF_DOTS;
    float* gm    = S + OFF_M;
    float* gl    = S + OFF_L;
    float* ao    = S + OFF_AO;

    // 1. layernorm
    ln_kernel<<<N_TOK, 256>>>(x, ln_g, ln_b, xn);

    // 2. q = xn@Wq, kv = xn@Wkv
    gemm2_kernel<128, false><<<dim3(INNER / 128, N_TOK / 128, 1), 256>>>(
        xn, Wq, c1, DIMX, DIMX, INNER, INNER, 0, 0, 0, 1.f, nullptr);
    gemm2_kernel<128, false><<<dim3(2 * INNER / 128, N_TOK / 128, 1), 256>>>(
        xn, Wkv, c2, DIMX, DIMX, 2 * INNER, 2 * INNER, 0, 0, 0, 1.f, nullptr);

    // 3. remap to per-head layout
    remap_qkv<<<(N_TOK * INNER + 255) / 256, 256>>>(c1, c2, q, k, v);

    // 4. raw(scaled) = SCALE * q @ k^T  -> dots2 interleaved [i][h][j]
    gemm2_kernel<128, true><<<dim3(N_TOK / 128, N_TOK / 128, HEADS), 256>>>(
        q, k, dots2, DHEAD, DHEAD, DHEAD, HEADS * N_TOK,
        (long long)N_TOK * DHEAD, (long long)N_TOK * DHEAD, (long long)N_TOK,
        SCALE_C, nullptr);

    // 5. blended (to output) + mix_pre (in place) + softmax stats
    blend_kernel<<<N_TOK, 256>>>(dots2, h_in, mix_pre, blended_out, gm, gl);

    // 6. normalize + mix_post (in place)
    mixpost_kernel<<<dim3(N_TOK / 1024, N_TOK, 1), 256>>>(dots2, mix_post, gm, gl);

    // 7. out_heads = attn @ v -> ao[i][g*64+d]
    gemm2_kernel<64, false><<<dim3(1, N_TOK / 128, HEADS), 256>>>(
        dots2, v, ao, N_TOK, HEADS * N_TOK, DHEAD, INNER,
        (long long)N_TOK, (long long)N_TOK * DHEAD, (long long)DHEAD,
        1.f, nullptr);

    // 8. out = ao @ Wout + bout
    gemm2_kernel<128, false><<<dim3(DIMX / 128, N_TOK / 128, 1), 256>>>(
        ao, Wout, out, INNER, INNER, DIMX, DIMX, 0, 0, 0, 1.f, bout);

    (void)in_sizes; (void)n_in; (void)out_size;
}

// round 3
// speedup vs baseline: 3.1021x; 1.5873x over previous
#include <cuda_runtime.h>
#include <cuda_bf16.h>
#include <math.h>
#include <stdint.h>

#define N_TOK 2048
#define DIMX  1024
#define HEADS 16
#define DHEAD 64
#define INNER 1024
#define NQKV  3072
#define ALPHA_C 0.45f
#define SCALE_C 0.125f

typedef __nv_bfloat16 bf16;
typedef __nv_bfloat162 bf162;

// ---------------- device buffers ----------------
__device__ __align__(256) float g_c12[(size_t)N_TOK * NQKV];
__device__ __align__(256) float g_dots[(size_t)HEADS * N_TOK * N_TOK];
__device__ __align__(256) float g_gm[HEADS * N_TOK];
__device__ __align__(256) float g_gl[HEADS * N_TOK];
__device__ __align__(256) bf16  g_xnh[(size_t)N_TOK * DIMX];
__device__ __align__(256) bf16  g_xnl[(size_t)N_TOK * DIMX];
__device__ __align__(256) bf16  g_wqkvh[(size_t)NQKV * DIMX];
__device__ __align__(256) bf16  g_wqkvl[(size_t)NQKV * DIMX];
__device__ __align__(256) bf16  g_woh[(size_t)DIMX * INNER];
__device__ __align__(256) bf16  g_wol[(size_t)DIMX * INNER];
__device__ __align__(256) bf16  g_qh[(size_t)HEADS * N_TOK * DHEAD];
__device__ __align__(256) bf16  g_ql[(size_t)HEADS * N_TOK * DHEAD];
__device__ __align__(256) bf16  g_kh[(size_t)HEADS * N_TOK * DHEAD];
__device__ __align__(256) bf16  g_kl[(size_t)HEADS * N_TOK * DHEAD];
__device__ __align__(256) bf16  g_vth[(size_t)HEADS * DHEAD * N_TOK];
__device__ __align__(256) bf16  g_vtl[(size_t)HEADS * DHEAD * N_TOK];
__device__ __align__(256) bf16  g_ath[(size_t)HEADS * N_TOK * N_TOK];
__device__ __align__(256) bf16  g_atl[(size_t)HEADS * N_TOK * N_TOK];
__device__ __align__(256) bf16  g_aoh[(size_t)N_TOK * INNER];
__device__ __align__(256) bf16  g_aol[(size_t)N_TOK * INNER];

// ---------------- helpers ----------------
__device__ __forceinline__ uint32_t s2u(const void* p) {
    return (uint32_t)__cvta_generic_to_shared(p);
}
__device__ __forceinline__ void cp16(uint32_t d, const void* g) {
    asm volatile("cp.async.cg.shared.global [%0],[%1],16;" :: "r"(d), "l"(g));
}
__device__ __forceinline__ void cpcommit() { asm volatile("cp.async.commit_group;"); }
template<int Nw> __device__ __forceinline__ void cpwait() {
    asm volatile("cp.async.wait_group %0;" :: "n"(Nw));
}
__device__ __forceinline__ void ldsm4(uint32_t* r, uint32_t addr) {
    asm volatile("ldmatrix.sync.aligned.m8n8.x4.shared.b16 {%0,%1,%2,%3},[%4];"
                 : "=r"(r[0]), "=r"(r[1]), "=r"(r[2]), "=r"(r[3]) : "r"(addr));
}
__device__ __forceinline__ void mma_bf(float* d, const uint32_t* a, uint32_t b0, uint32_t b1) {
    asm volatile(
        "mma.sync.aligned.m16n8k16.row.col.f32.bf16.bf16.f32 "
        "{%0,%1,%2,%3},{%4,%5,%6,%7},{%8,%9},{%0,%1,%2,%3};"
        : "+f"(d[0]), "+f"(d[1]), "+f"(d[2]), "+f"(d[3])
        : "r"(a[0]), "r"(a[1]), "r"(a[2]), "r"(a[3]), "r"(b0), "r"(b1));
}
__device__ __forceinline__ void split2(float v, bf16& h, bf16& l) {
    h = __float2bfloat16(v);
    l = __float2bfloat16(v - __bfloat162float(h));
}

// ---------------- layernorm + split ----------------
__global__ void ln_split_kernel(const float* __restrict__ x,
                                const float* __restrict__ gam,
                                const float* __restrict__ bet,
                                bf16* __restrict__ oh, bf16* __restrict__ ol)
{
    int row = blockIdx.x;
    const float* xr = x + (size_t)row * DIMX;
    float s = 0.f, s2 = 0.f;
    for (int c = threadIdx.x; c < DIMX; c += blockDim.x) {
        float v = xr[c];
        s += v; s2 += v * v;
    }
    __shared__ float red[64];
    for (int o = 16; o > 0; o >>= 1) {
        s  += __shfl_xor_sync(0xffffffffu, s,  o);
        s2 += __shfl_xor_sync(0xffffffffu, s2, o);
    }
    int warp = threadIdx.x >> 5, lane = threadIdx.x & 31;
    int nwarp = blockDim.x >> 5;
    if (lane == 0) { red[warp] = s; red[warp + 32] = s2; }
    __syncthreads();
    if (warp == 0) {
        s  = (lane < nwarp) ? red[lane] : 0.f;
        s2 = (lane < nwarp) ? red[lane + 32] : 0.f;
        for (int o = 16; o > 0; o >>= 1) {
            s  += __shfl_xor_sync(0xffffffffu, s,  o);
            s2 += __shfl_xor_sync(0xffffffffu, s2, o);
        }
        if (lane == 0) { red[0] = s; red[1] = s2; }
    }
    __syncthreads();
    float mean = red[0] * (1.f / DIMX);
    float var  = red[1] * (1.f / DIMX) - mean * mean;
    float inv  = rsqrtf(var + 1e-5f);
    for (int c = threadIdx.x; c < DIMX; c += blockDim.x) {
        float y = (xr[c] - mean) * inv * gam[c] + bet[c];
        bf16 h, l; split2(y, h, l);
        oh[(size_t)row * DIMX + c] = h;
        ol[(size_t)row * DIMX + c] = l;
    }
}

// ---------------- transpose + split: out[c][r] = split(in[r][c]) ----------------
__global__ void tsplit_kernel(const float* __restrict__ in, int ldin, long long sIn,
                              bf16* __restrict__ oh, bf16* __restrict__ ol,
                              int ldout, long long sOut, int R, int C)
{
    __shared__ float t[32][33];
    in += (size_t)blockIdx.z * sIn;
    oh += (size_t)blockIdx.z * sOut;
    ol += (size_t)blockIdx.z * sOut;
    int r0 = blockIdx.y * 32, c0 = blockIdx.x * 32;
    int tx = threadIdx.x & 31, ty = threadIdx.x >> 5;   // 256 thr = 32x8
#pragma unroll
    for (int i = 0; i < 32; i += 8) {
        int r = r0 + ty + i;
        if (r < R && c0 + tx < C) t[ty + i][tx] = in[(size_t)r * ldin + c0 + tx];
    }
    __syncthreads();
#pragma unroll
    for (int i = 0; i < 32; i += 8) {
        int c = c0 + ty + i, r = r0 + tx;
        if (c < C && r < R) {
            float v = t[tx][ty + i];
            bf16 h, l; split2(v, h, l);
            oh[(size_t)c * ldout + r] = h;
            ol[(size_t)c * ldout + r] = l;
        }
    }
}

// ---------------- remap + split: c12 (i, col) -> q/k [h][i][d] bf16 hi/lo ----------------
__global__ void remap_split(const float* __restrict__ c12,
                            bf16* __restrict__ qh, bf16* __restrict__ ql,
                            bf16* __restrict__ kh, bf16* __restrict__ kl)
{
    int idx = blockIdx.x * blockDim.x + threadIdx.x;
    if (idx >= N_TOK * INNER) return;
    int i = idx >> 10, col = idx & 1023;
    int h = col >> 6, d = col & 63;
    float qv = c12[(size_t)i * NQKV + col];
    float kv = c12[(size_t)i * NQKV + INNER + col];
    size_t dst = ((size_t)h * N_TOK + i) * DHEAD + d;
    bf16 a, b;
    split2(qv, a, b); qh[dst] = a; ql[dst] = b;
    split2(kv, a, b); kh[dst] = a; kl[dst] = b;
}

// ---------------- bf16x3 tensor-core GEMM ----------------
// C[M,N] = alpha * A @ B^T  (A: [M,K] k-contig hi/lo, B: [N,K] k-contig hi/lo)
// SPLIT=false: C fp32 (+bias). SPLIT=true: Chi/Clo bf16.
template<int BM, int BN, int WM, int WN, bool SPLIT>
__global__ void __launch_bounds__(256)
gemm_bf3(const bf16* __restrict__ Ahi, const bf16* __restrict__ Alo,
         const bf16* __restrict__ Bhi, const bf16* __restrict__ Blo,
         float* __restrict__ C, bf16* __restrict__ Chi, bf16* __restrict__ Clo,
         int K, int lda, int ldb, int ldc,
         long long sA, long long sB, long long sC,
         float alpha, const float* __restrict__ bias)
{
    constexpr int MI  = WM / 16;
    constexpr int NJ  = WN / 16;
    constexpr int NJ2 = WN / 8;
    constexpr int NA  = BM * 8 / 256;
    constexpr int NB  = BN * 8 / 256;
    constexpr int SS  = (2 * BM + 2 * BN) * 64;   // halves per stage
    constexpr int WNN = BN / WN;

    extern __shared__ bf16 sm[];

    Ahi += (size_t)blockIdx.z * sA;  Alo += (size_t)blockIdx.z * sA;
    Bhi += (size_t)blockIdx.z * sB;  Blo += (size_t)blockIdx.z * sB;
    if (SPLIT) { Chi += (size_t)blockIdx.z * sC; Clo += (size_t)blockIdx.z * sC; }
    else       { C   += (size_t)blockIdx.z * sC; }

    const int bm = blockIdx.y * BM, bn = blockIdx.x * BN;
    const int tid = threadIdx.x, lane = tid & 31, wid = tid >> 5;
    const int wm0 = (wid / WNN) * WM, wn0 = (wid % WNN) * WN;

    float acc[MI][NJ2][4];
#pragma unroll
    for (int i = 0; i < MI; i++)
#pragma unroll
        for (int j = 0; j < NJ2; j++) {
            acc[i][j][0] = 0.f; acc[i][j][1] = 0.f;
            acc[i][j][2] = 0.f; acc[i][j][3] = 0.f;
        }

    auto issue = [&](int kt, int stg) {
        bf16* sA_hi = sm + stg * SS;
        bf16* sA_lo = sA_hi + BM * 64;
        bf16* sB_hi = sA_lo + BM * 64;
        bf16* sB_lo = sB_hi + BN * 64;
#pragma unroll
        for (int i = 0; i < NA; i++) {
            int id = tid + i * 256, r = id >> 3, c = id & 7;
            size_t go = (size_t)(bm + r) * lda + kt * 64 + c * 8;
            int so = r * 64 + ((c ^ (r & 7)) << 3);
            cp16(s2u(sA_hi + so), Ahi + go);
            cp16(s2u(sA_lo + so), Alo + go);
        }
#pragma unroll
        for (int i = 0; i < NB; i++) {
            int id = tid + i * 256, r = id >> 3, c = id & 7;
            size_t go = (size_t)(bn + r) * ldb + kt * 64 + c * 8;
            int so = r * 64 + ((c ^ (r & 7)) << 3);
            cp16(s2u(sB_hi + so), Bhi + go);
            cp16(s2u(sB_lo + so), Blo + go);
        }
    };

    const int KT = K >> 6;
    issue(0, 0); cpcommit();

    for (int kt = 0; kt < KT; kt++) {
        int cur = kt & 1;
        if (kt + 1 < KT) { issue(kt + 1, cur ^ 1); cpcommit(); cpwait<1>(); }
        else             { cpwait<0>(); }
        __syncthreads();

        const bf16* sA_hi = sm + cur * SS;
        const bf16* sA_lo = sA_hi + BM * 64;
        const bf16* sB_hi = sA_lo + BM * 64;
        const bf16* sB_lo = sB_hi + BN * 64;

#pragma unroll
        for (int s = 0; s < 4; s++) {
            const int c0 = 2 * s;
            uint32_t ah[MI][4], al[MI][4];
#pragma unroll
            for (int mi = 0; mi < MI; mi++) {
                int row = wm0 + mi * 16 + (lane & 15);
                int ch  = c0 + (lane >> 4);
                int off = row * 64 + ((ch ^ (row & 7)) << 3);
                ldsm4(ah[mi], s2u(sA_hi + off));
                ldsm4(al[mi], s2u(sA_lo + off));
            }
#pragma unroll
            for (int nj = 0; nj < NJ; nj++) {
                uint32_t bh[4], bl[4];
                int rowb = wn0 + nj * 16 + (lane & 15);
                int ch   = c0 + (lane >> 4);
                int off  = rowb * 64 + ((ch ^ (rowb & 7)) << 3);
                ldsm4(bh, s2u(sB_hi + off));
                ldsm4(bl, s2u(sB_lo + off));
#pragma unroll
                for (int mi = 0; mi < MI; mi++) {
                    mma_bf(acc[mi][2 * nj],     ah[mi], bh[0], bh[2]);
                    mma_bf(acc[mi][2 * nj],     ah[mi], bl[0], bl[2]);
                    mma_bf(acc[mi][2 * nj],     al[mi], bh[0], bh[2]);
                    mma_bf(acc[mi][2 * nj + 1], ah[mi], bh[1], bh[3]);
                    mma_bf(acc[mi][2 * nj + 1], ah[mi], bl[1], bl[3]);
                    mma_bf(acc[mi][2 * nj + 1], al[mi], bh[1], bh[3]);
                }
            }
        }
        __syncthreads();
    }

    // ---- epilogue ----
#pragma unroll
    for (int mi = 0; mi < MI; mi++) {
#pragma unroll
        for (int nj2 = 0; nj2 < NJ2; nj2++) {
            int r0  = bm + wm0 + mi * 16 + (lane >> 2);
            int col = bn + wn0 + nj2 * 8 + (lane & 3) * 2;
            float v0 = acc[mi][nj2][0] * alpha, v1 = acc[mi][nj2][1] * alpha;
            float v2 = acc[mi][nj2][2] * alpha, v3 = acc[mi][nj2][3] * alpha;
            if (SPLIT) {
                bf16 h0, l0, h1, l1;
                bf162 ph, pl;
                size_t o0 = (size_t)r0 * ldc + col;
                split2(v0, h0, l0); split2(v1, h1, l1);
                ph.x = h0; ph.y = h1; pl.x = l0; pl.y = l1;
                *(bf162*)&Chi[o0] = ph; *(bf162*)&Clo[o0] = pl;
                size_t o1 = o0 + (size_t)8 * ldc;
                split2(v2, h0, l0); split2(v3, h1, l1);
                ph.x = h0; ph.y = h1; pl.x = l0; pl.y = l1;
                *(bf162*)&Chi[o1] = ph; *(bf162*)&Clo[o1] = pl;
            } else {
                if (bias) {
                    float b0 = bias[col], b1 = bias[col + 1];
                    v0 += b0; v1 += b1; v2 += b0; v3 += b1;
                }
                *(float2*)&C[(size_t)r0 * ldc + col]       = make_float2(v0, v1);
                *(float2*)&C[(size_t)(r0 + 8) * ldc + col] = make_float2(v2, v3);
            }
        }
    }
}

// ---------------- blend + mix_pre + online softmax stats ----------------
__global__ void __launch_bounds__(256)
blend_kernel(float* __restrict__ dots2, const float* __restrict__ hin,
             const float* __restrict__ mp, float* __restrict__ blended,
             float* __restrict__ gm, float* __restrict__ gl)
{
    __shared__ float smix[HEADS * HEADS];
    __shared__ float redm[8][HEADS], redl[8][HEADS];
    const int i = blockIdx.x, tid = threadIdx.x;
    smix[tid & 255] = mp[tid & 255];
    __syncthreads();

    const size_t rbase = (size_t)i * (HEADS * N_TOK);
    const size_t hbase = (size_t)i * N_TOK;
    const size_t sH = (size_t)N_TOK * N_TOK;

    float m[HEADS], l[HEADS];
#pragma unroll
    for (int g = 0; g < HEADS; g++) { m[g] = -INFINITY; l[g] = 0.f; }

    for (int j = tid * 4; j < N_TOK; j += 1024) {
        float4 bl4[HEADS];
#pragma unroll
        for (int h = 0; h < HEADS; h++) {
            float4 r  = *(const float4*)&dots2[rbase + h * N_TOK + j];
            float4 hv = *(const float4*)&hin[(size_t)h * sH + hbase + j];
            float4 b;
            b.x = ALPHA_C * r.x + (1.f - ALPHA_C) * hv.x;
            b.y = ALPHA_C * r.y + (1.f - ALPHA_C) * hv.y;
            b.z = ALPHA_C * r.z + (1.f - ALPHA_C) * hv.z;
            b.w = ALPHA_C * r.w + (1.f - ALPHA_C) * hv.w;
            *(float4*)&blended[(size_t)h * sH + hbase + j] = b;
            bl4[h] = b;
        }
#pragma unroll
        for (int g = 0; g < HEADS; g++) {
            float4 d = make_float4(0.f, 0.f, 0.f, 0.f);
#pragma unroll
            for (int h = 0; h < HEADS; h++) {
                float w = smix[h * HEADS + g];
                d.x += bl4[h].x * w; d.y += bl4[h].y * w;
                d.z += bl4[h].z * w; d.w += bl4[h].w * w;
            }
            *(float4*)&dots2[rbase + g * N_TOK + j] = d;
            float mx = fmaxf(fmaxf(d.x, d.y), fmaxf(d.z, d.w));
            float nm = fmaxf(m[g], mx);
            l[g] = l[g] * __expf(m[g] - nm)
                 + __expf(d.x - nm) + __expf(d.y - nm)
                 + __expf(d.z - nm) + __expf(d.w - nm);
            m[g] = nm;
        }
    }

#pragma unroll
    for (int g = 0; g < HEADS; g++) {
        for (int o = 16; o > 0; o >>= 1) {
            float m2 = __shfl_xor_sync(0xffffffffu, m[g], o);
            float l2 = __shfl_xor_sync(0xffffffffu, l[g], o);
            float nm = fmaxf(m[g], m2);
            l[g] = l[g] * __expf(m[g] - nm) + l2 * __expf(m2 - nm);
            m[g] = nm;
        }
    }
    int warp = tid >> 5, lane = tid & 31;
    if (lane == 0) {
#pragma unroll
        for (int g = 0; g < HEADS; g++) { redm[warp][g] = m[g]; redl[warp][g] = l[g]; }
    }
    __syncthreads();
    if (tid < HEADS) {
        int g = tid;
        float M = redm[0][g], L = redl[0][g];
#pragma unroll
        for (int w = 1; w < 8; w++) {
            float m2 = redm[w][g], l2 = redl[w][g];
            float nm = fmaxf(M, m2);
            L = L * __expf(M - nm) + l2 * __expf(m2 - nm);
            M = nm;
        }
        gm[g * N_TOK + i] = M;
        gl[g * N_TOK + i] = L;
    }
}

// ---------------- normalize + mix_post -> attn bf16 hi/lo ----------------
__global__ void __launch_bounds__(256)
mixpost_kernel(const float* __restrict__ dots2, const float* __restrict__ mp,
               const float* __restrict__ gm, const float* __restrict__ gl,
               bf16* __restrict__ ath, bf16* __restrict__ atl)
{
    __shared__ float smix[HEADS * HEADS];
    const int tid = threadIdx.x;
    smix[tid & 255] = mp[tid & 255];
    __syncthreads();

    const int i = blockIdx.y;
    const int j = (blockIdx.x * 256 + tid) * 4;
    const size_t rbase = (size_t)i * (HEADS * N_TOK);

    float4 p4[HEADS];
#pragma unroll
    for (int h = 0; h < HEADS; h++) {
        float mh = gm[h * N_TOK + i];
        float li = 1.0f / gl[h * N_TOK + i];
        float4 d = *(const float4*)&dots2[rbase + h * N_TOK + j];
        p4[h].x = __expf(d.x - mh) * li;
        p4[h].y = __expf(d.y - mh) * li;
        p4[h].z = __expf(d.z - mh) * li;
        p4[h].w = __expf(d.w - mh) * li;
    }
#pragma unroll
    for (int g = 0; g < HEADS; g++) {
        float4 a = make_float4(0.f, 0.f, 0.f, 0.f);
#pragma unroll
        for (int h = 0; h < HEADS; h++) {
            float w = smix[h * HEADS + g];
            a.x += p4[h].x * w; a.y += p4[h].y * w;
            a.z += p4[h].z * w; a.w += p4[h].w * w;
        }
        bf16 h0, l0, h1, l1;
        bf162 ph, pl;
        size_t o = rbase + g * N_TOK + j;
        split2(a.x, h0, l0); split2(a.y, h1, l1);
        ph.x = h0; ph.y = h1; pl.x = l0; pl.y = l1;
        ((bf162*)&ath[o])[0] = ph; ((bf162*)&atl[o])[0] = pl;
        split2(a.z, h0, l0); split2(a.w, h1, l1);
        ph.x = h0; ph.y = h1; pl.x = l0; pl.y = l1;
        ((bf162*)&ath[o])[1] = ph; ((bf162*)&atl[o])[1] = pl;
    }
}

// ---------------- launch ----------------
extern "C" void kernel_launch(void* const* d_in, const int* in_sizes, int n_in,
                              void* d_out, int out_size)
{
    const float* x        = (const float*)d_in[0];
    const float* h_in     = (const float*)d_in[1];
    const float* ln_g     = (const float*)d_in[2];
    const float* ln_b     = (const float*)d_in[3];
    const float* Wq       = (const float*)d_in[4];
    const float* Wkv      = (const float*)d_in[5];
    const float* mix_pre  = (const float*)d_in[6];
    const float* mix_post = (const float*)d_in[7];
    const float* Wout     = (const float*)d_in[8];
    const float* bout     = (const float*)d_in[9];

    float* out = (float*)d_out;
    float* blended_out = out + (size_t)N_TOK * DIMX;

    float *c12, *dots, *gm, *gl;
    bf16 *xnh, *xnl, *wqkvh, *wqkvl, *woh, *wol;
    bf16 *qh, *ql, *kh, *kl, *vth, *vtl, *ath, *atl, *aoh, *aol;
    cudaGetSymbolAddress((void**)&c12,  g_c12);
    cudaGetSymbolAddress((void**)&dots, g_dots);
    cudaGetSymbolAddress((void**)&gm,   g_gm);
    cudaGetSymbolAddress((void**)&gl,   g_gl);
    cudaGetSymbolAddress((void**)&xnh,  g_xnh);
    cudaGetSymbolAddress((void**)&xnl,  g_xnl);
    cudaGetSymbolAddress((void**)&wqkvh, g_wqkvh);
    cudaGetSymbolAddress((void**)&wqkvl, g_wqkvl);
    cudaGetSymbolAddress((void**)&woh,  g_woh);
    cudaGetSymbolAddress((void**)&wol,  g_wol);
    cudaGetSymbolAddress((void**)&qh,   g_qh);
    cudaGetSymbolAddress((void**)&ql,   g_ql);
    cudaGetSymbolAddress((void**)&kh,   g_kh);
    cudaGetSymbolAddress((void**)&kl,   g_kl);
    cudaGetSymbolAddress((void**)&vth,  g_vth);
    cudaGetSymbolAddress((void**)&vtl,  g_vtl);
    cudaGetSymbolAddress((void**)&ath,  g_ath);
    cudaGetSymbolAddress((void**)&atl,  g_atl);
    cudaGetSymbolAddress((void**)&aoh,  g_aoh);
    cudaGetSymbolAddress((void**)&aol,  g_aol);

    // dynamic smem limits for the two gemm instantiations
    const int SM_BIG = (2 * 128 + 2 * 128) * 64 * 2 * 2;  // 131072 B
    const int SM_AV  = (2 * 128 + 2 * 64)  * 64 * 2 * 2;  //  98304 B
    cudaFuncSetAttribute(gemm_bf3<128, 128, 64, 32, false>,
                         cudaFuncAttributeMaxDynamicSharedMemorySize, SM_BIG);
    cudaFuncSetAttribute(gemm_bf3<128, 64, 32, 32, true>,
                         cudaFuncAttributeMaxDynamicSharedMemorySize, SM_AV);

    // 1. layernorm + split
    ln_split_kernel<<<N_TOK, 256>>>(x, ln_g, ln_b, xnh, xnl);

    // 2. weight transposes + split (K-major B operands)
    tsplit_kernel<<<dim3(32, 32, 1), 256>>>(Wq, INNER, 0, wqkvh, wqkvl, DIMX, 0, DIMX, INNER);
    tsplit_kernel<<<dim3(64, 32, 1), 256>>>(Wkv, 2 * INNER, 0,
                                            wqkvh + (size_t)INNER * DIMX,
                                            wqkvl + (size_t)INNER * DIMX,
                                            DIMX, 0, DIMX, 2 * INNER);
    tsplit_kernel<<<dim3(32, 32, 1), 256>>>(Wout, DIMX, 0, woh, wol, INNER, 0, INNER, DIMX);

    // 3. c12 = xn @ [Wq|Wkv]   (M=2048, N=3072, K=1024)
    gemm_bf3<128, 128, 64, 32, false><<<dim3(NQKV / 128, N_TOK / 128, 1), 256, SM_BIG>>>(
        xnh, xnl, wqkvh, wqkvl, c12, nullptr, nullptr,
        DIMX, DIMX, DIMX, NQKV, 0, 0, 0, 1.f, nullptr);

    // 4. remap q/k to [h][i][d] hi/lo
    remap_split<<<(N_TOK * INNER + 255) / 256, 256>>>(c12, qh, ql, kh, kl);

    // 5. v^T per head: [h][d][j] hi/lo (batched transpose of c12 v-columns)
    tsplit_kernel<<<dim3(2, 64, HEADS), 256>>>(c12 + 2 * INNER, NQKV, DHEAD,
                                               vth, vtl, N_TOK,
                                               (long long)DHEAD * N_TOK,
                                               N_TOK, DHEAD);

    // 6. dots[i][h][j] = SCALE * q @ k^T   (per head; M=N=2048, K=64)
    gemm_bf3<128, 128, 64, 32, false><<<dim3(N_TOK / 128, N_TOK / 128, HEADS), 256, SM_BIG>>>(
        qh, ql, kh, kl, dots, nullptr, nullptr,
        DHEAD, DHEAD, DHEAD, HEADS * N_TOK,
        (long long)N_TOK * DHEAD, (long long)N_TOK * DHEAD, (long long)N_TOK,
        SCALE_C, nullptr);

    // 7. blended (to output) + mix_pre (in place) + softmax stats
    blend_kernel<<<N_TOK, 256>>>(dots, h_in, mix_pre, blended_out, gm, gl);

    // 8. normalize + mix_post -> attn bf16 hi/lo
    mixpost_kernel<<<dim3(N_TOK / 1024, N_TOK, 1), 256>>>(dots, mix_post, gm, gl, ath, atl);

    // 9. ao = attn @ v  (per head; M=2048, N=64, K=2048) -> split bf16 out
    gemm_bf3<128, 64, 32, 32, true><<<dim3(1, N_TOK / 128, HEADS), 256, SM_AV>>>(
        ath, atl, vth, vtl, nullptr, aoh, aol,
        N_TOK, HEADS * N_TOK, N_TOK, INNER,
        (long long)N_TOK, (long long)DHEAD * N_TOK, (long long)DHEAD,
        1.f, nullptr);

    // 10. out = ao @ Wout + bout  (M=2048, N=1024, K=1024)
    gemm_bf3<128, 128, 64, 32, false><<<dim3(DIMX / 128, N_TOK / 128, 1), 256, SM_BIG>>>(
        aoh, aol, woh, wol, out, nullptr, nullptr,
        INNER, INNER, INNER, DIMX, 0, 0, 0, 1.f, bout);

    (void)in_sizes; (void)n_in; (void)out_size;
}

// round 4
// speedup vs baseline: 5.2402x; 1.6892x over previous
#include <cuda_runtime.h>
#include <cuda_bf16.h>
#include <math.h>
#include <stdint.h>

#define N_TOK 2048
#define DIMX  1024
#define HEADS 16
#define DHEAD 64
#define INNER 1024
#define NQKV  3072
#define ALPHA_C 0.45f
#define SCALE_C 0.125f

typedef __nv_bfloat16 bf16;
typedef __nv_bfloat162 bf162;

// ---------------- device buffers ----------------
__device__ __align__(256) float g_c12[(size_t)N_TOK * NQKV];
__device__ __align__(256) bf16  g_xnh[(size_t)N_TOK * DIMX];
__device__ __align__(256) bf16  g_xnl[(size_t)N_TOK * DIMX];
__device__ __align__(256) bf16  g_wqkvh[(size_t)NQKV * DIMX];
__device__ __align__(256) bf16  g_wqkvl[(size_t)NQKV * DIMX];
__device__ __align__(256) bf16  g_woh[(size_t)DIMX * INNER];
__device__ __align__(256) bf16  g_wol[(size_t)DIMX * INNER];
__device__ __align__(256) bf16  g_qh[(size_t)HEADS * N_TOK * DHEAD];
__device__ __align__(256) bf16  g_ql[(size_t)HEADS * N_TOK * DHEAD];
__device__ __align__(256) bf16  g_kh[(size_t)HEADS * N_TOK * DHEAD];
__device__ __align__(256) bf16  g_kl[(size_t)HEADS * N_TOK * DHEAD];
__device__ __align__(256) bf16  g_vth[(size_t)HEADS * DHEAD * N_TOK];
__device__ __align__(256) bf16  g_vtl[(size_t)HEADS * DHEAD * N_TOK];
__device__ __align__(256) bf16  g_ath[(size_t)HEADS * N_TOK * N_TOK];
__device__ __align__(256) bf16  g_atl[(size_t)HEADS * N_TOK * N_TOK];
__device__ __align__(256) bf16  g_aoh[(size_t)N_TOK * INNER];
__device__ __align__(256) bf16  g_aol[(size_t)N_TOK * INNER];

// ---------------- helpers ----------------
__device__ __forceinline__ uint32_t s2u(const void* p) {
    return (uint32_t)__cvta_generic_to_shared(p);
}
__device__ __forceinline__ void cp16(uint32_t d, const void* g) {
    asm volatile("cp.async.cg.shared.global [%0],[%1],16;" :: "r"(d), "l"(g));
}
__device__ __forceinline__ void cpcommit() { asm volatile("cp.async.commit_group;"); }
template<int Nw> __device__ __forceinline__ void cpwait() {
    asm volatile("cp.async.wait_group %0;" :: "n"(Nw));
}
__device__ __forceinline__ void ldsm4(uint32_t* r, uint32_t addr) {
    asm volatile("ldmatrix.sync.aligned.m8n8.x4.shared.b16 {%0,%1,%2,%3},[%4];"
                 : "=r"(r[0]), "=r"(r[1]), "=r"(r[2]), "=r"(r[3]) : "r"(addr));
}
__device__ __forceinline__ void mma_bf(float* d, const uint32_t* a, uint32_t b0, uint32_t b1) {
    asm volatile(
        "mma.sync.aligned.m16n8k16.row.col.f32.bf16.bf16.f32 "
        "{%0,%1,%2,%3},{%4,%5,%6,%7},{%8,%9},{%0,%1,%2,%3};"
        : "+f"(d[0]), "+f"(d[1]), "+f"(d[2]), "+f"(d[3])
        : "r"(a[0]), "r"(a[1]), "r"(a[2]), "r"(a[3]), "r"(b0), "r"(b1));
}
__device__ __forceinline__ void split2(float v, bf16& h, bf16& l) {
    h = __float2bfloat16(v);
    l = __float2bfloat16(v - __bfloat162float(h));
}

// ---------------- layernorm + split ----------------
__global__ void ln_split_kernel(const float* __restrict__ x,
                                const float* __restrict__ gam,
                                const float* __restrict__ bet,
                                bf16* __restrict__ oh, bf16* __restrict__ ol)
{
    int row = blockIdx.x;
    const float* xr = x + (size_t)row * DIMX;
    float s = 0.f, s2 = 0.f;
    for (int c = threadIdx.x; c < DIMX; c += blockDim.x) {
        float v = xr[c];
        s += v; s2 += v * v;
    }
    __shared__ float red[64];
    for (int o = 16; o > 0; o >>= 1) {
        s  += __shfl_xor_sync(0xffffffffu, s,  o);
        s2 += __shfl_xor_sync(0xffffffffu, s2, o);
    }
    int warp = threadIdx.x >> 5, lane = threadIdx.x & 31;
    int nwarp = blockDim.x >> 5;
    if (lane == 0) { red[warp] = s; red[warp + 32] = s2; }
    __syncthreads();
    if (warp == 0) {
        s  = (lane < nwarp) ? red[lane] : 0.f;
        s2 = (lane < nwarp) ? red[lane + 32] : 0.f;
        for (int o = 16; o > 0; o >>= 1) {
            s  += __shfl_xor_sync(0xffffffffu, s,  o);
            s2 += __shfl_xor_sync(0xffffffffu, s2, o);
        }
        if (lane == 0) { red[0] = s; red[1] = s2; }
    }
    __syncthreads();
    float mean = red[0] * (1.f / DIMX);
    float var  = red[1] * (1.f / DIMX) - mean * mean;
    float inv  = rsqrtf(var + 1e-5f);
    for (int c = threadIdx.x; c < DIMX; c += blockDim.x) {
        float y = (xr[c] - mean) * inv * gam[c] + bet[c];
        bf16 h, l; split2(y, h, l);
        oh[(size_t)row * DIMX + c] = h;
        ol[(size_t)row * DIMX + c] = l;
    }
}

// ---------------- transpose + split ----------------
__global__ void tsplit_kernel(const float* __restrict__ in, int ldin, long long sIn,
                              bf16* __restrict__ oh, bf16* __restrict__ ol,
                              int ldout, long long sOut, int R, int C)
{
    __shared__ float t[32][33];
    in += (size_t)blockIdx.z * sIn;
    oh += (size_t)blockIdx.z * sOut;
    ol += (size_t)blockIdx.z * sOut;
    int r0 = blockIdx.y * 32, c0 = blockIdx.x * 32;
    int tx = threadIdx.x & 31, ty = threadIdx.x >> 5;
#pragma unroll
    for (int i = 0; i < 32; i += 8) {
        int r = r0 + ty + i;
        if (r < R && c0 + tx < C) t[ty + i][tx] = in[(size_t)r * ldin + c0 + tx];
    }
    __syncthreads();
#pragma unroll
    for (int i = 0; i < 32; i += 8) {
        int c = c0 + ty + i, r = r0 + tx;
        if (c < C && r < R) {
            float v = t[tx][ty + i];
            bf16 h, l; split2(v, h, l);
            oh[(size_t)c * ldout + r] = h;
            ol[(size_t)c * ldout + r] = l;
        }
    }
}

// ---------------- remap + split ----------------
__global__ void remap_split(const float* __restrict__ c12,
                            bf16* __restrict__ qh, bf16* __restrict__ ql,
                            bf16* __restrict__ kh, bf16* __restrict__ kl)
{
    int idx = blockIdx.x * blockDim.x + threadIdx.x;
    if (idx >= N_TOK * INNER) return;
    int i = idx >> 10, col = idx & 1023;
    int h = col >> 6, d = col & 63;
    float qv = c12[(size_t)i * NQKV + col];
    float kv = c12[(size_t)i * NQKV + INNER + col];
    size_t dst = ((size_t)h * N_TOK + i) * DHEAD + d;
    bf16 a, b;
    split2(qv, a, b); qh[dst] = a; ql[dst] = b;
    split2(kv, a, b); kh[dst] = a; kl[dst] = b;
}

// ---------------- bf16x3 tensor-core GEMM ----------------
// MODE 0: C fp32 (+bias). MODE 1: split to Chi/Clo bf16. MODE 2: blend —
// C = ALPHA*alpha*acc + (1-ALPHA)*Hm, same layout as C.
template<int BM, int BN, int WM, int WN, int MODE>
__global__ void __launch_bounds__(256)
gemm_bf3(const bf16* __restrict__ Ahi, const bf16* __restrict__ Alo,
         const bf16* __restrict__ Bhi, const bf16* __restrict__ Blo,
         float* __restrict__ C, bf16* __restrict__ Chi, bf16* __restrict__ Clo,
         const float* __restrict__ Hm,
         int K, int lda, int ldb, int ldc,
         long long sA, long long sB, long long sC,
         float alpha, const float* __restrict__ bias)
{
    constexpr int MI  = WM / 16;
    constexpr int NJ  = WN / 16;
    constexpr int NJ2 = WN / 8;
    constexpr int NA  = BM * 8 / 256;
    constexpr int NB  = BN * 8 / 256;
    constexpr int SS  = (2 * BM + 2 * BN) * 64;
    constexpr int WNN = BN / WN;

    extern __shared__ bf16 sm[];

    Ahi += (size_t)blockIdx.z * sA;  Alo += (size_t)blockIdx.z * sA;
    Bhi += (size_t)blockIdx.z * sB;  Blo += (size_t)blockIdx.z * sB;
    if (MODE == 1) { Chi += (size_t)blockIdx.z * sC; Clo += (size_t)blockIdx.z * sC; }
    else           { C   += (size_t)blockIdx.z * sC; }
    if (MODE == 2) { Hm  += (size_t)blockIdx.z * sC; }

    const int bm = blockIdx.y * BM, bn = blockIdx.x * BN;
    const int tid = threadIdx.x, lane = tid & 31, wid = tid >> 5;
    const int wm0 = (wid / WNN) * WM, wn0 = (wid % WNN) * WN;

    float acc[MI][NJ2][4];
#pragma unroll
    for (int i = 0; i < MI; i++)
#pragma unroll
        for (int j = 0; j < NJ2; j++) {
            acc[i][j][0] = 0.f; acc[i][j][1] = 0.f;
            acc[i][j][2] = 0.f; acc[i][j][3] = 0.f;
        }

    auto issue = [&](int kt, int stg) {
        bf16* sA_hi = sm + stg * SS;
        bf16* sA_lo = sA_hi + BM * 64;
        bf16* sB_hi = sA_lo + BM * 64;
        bf16* sB_lo = sB_hi + BN * 64;
#pragma unroll
        for (int i = 0; i < NA; i++) {
            int id = tid + i * 256, r = id >> 3, c = id & 7;
            size_t go = (size_t)(bm + r) * lda + kt * 64 + c * 8;
            int so = r * 64 + ((c ^ (r & 7)) << 3);
            cp16(s2u(sA_hi + so), Ahi + go);
            cp16(s2u(sA_lo + so), Alo + go);
        }
#pragma unroll
        for (int i = 0; i < NB; i++) {
            int id = tid + i * 256, r = id >> 3, c = id & 7;
            size_t go = (size_t)(bn + r) * ldb + kt * 64 + c * 8;
            int so = r * 64 + ((c ^ (r & 7)) << 3);
            cp16(s2u(sB_hi + so), Bhi + go);
            cp16(s2u(sB_lo + so), Blo + go);
        }
    };

    const int KT = K >> 6;
    issue(0, 0); cpcommit();

    for (int kt = 0; kt < KT; kt++) {
        int cur = kt & 1;
        if (kt + 1 < KT) { issue(kt + 1, cur ^ 1); cpcommit(); cpwait<1>(); }
        else             { cpwait<0>(); }
        __syncthreads();

        const bf16* sA_hi = sm + cur * SS;
        const bf16* sA_lo = sA_hi + BM * 64;
        const bf16* sB_hi = sA_lo + BM * 64;
        const bf16* sB_lo = sB_hi + BN * 64;

#pragma unroll
        for (int s = 0; s < 4; s++) {
            const int c0 = 2 * s;
            uint32_t ah[MI][4], al[MI][4];
#pragma unroll
            for (int mi = 0; mi < MI; mi++) {
                int row = wm0 + mi * 16 + (lane & 15);
                int ch  = c0 + (lane >> 4);
                int off = row * 64 + ((ch ^ (row & 7)) << 3);
                ldsm4(ah[mi], s2u(sA_hi + off));
                ldsm4(al[mi], s2u(sA_lo + off));
            }
#pragma unroll
            for (int nj = 0; nj < NJ; nj++) {
                uint32_t bh[4], bl[4];
                int rowb = wn0 + nj * 16 + (lane & 15);
                int ch   = c0 + (lane >> 4);
                int off  = rowb * 64 + ((ch ^ (rowb & 7)) << 3);
                ldsm4(bh, s2u(sB_hi + off));
                ldsm4(bl, s2u(sB_lo + off));
#pragma unroll
                for (int mi = 0; mi < MI; mi++) {
                    mma_bf(acc[mi][2 * nj],     ah[mi], bh[0], bh[2]);
                    mma_bf(acc[mi][2 * nj],     ah[mi], bl[0], bl[2]);
                    mma_bf(acc[mi][2 * nj],     al[mi], bh[0], bh[2]);
                    mma_bf(acc[mi][2 * nj + 1], ah[mi], bh[1], bh[3]);
                    mma_bf(acc[mi][2 * nj + 1], ah[mi], bl[1], bl[3]);
                    mma_bf(acc[mi][2 * nj + 1], al[mi], bh[1], bh[3]);
                }
            }
        }
        __syncthreads();
    }

    // ---- epilogue ----
#pragma unroll
    for (int mi = 0; mi < MI; mi++) {
#pragma unroll
        for (int nj2 = 0; nj2 < NJ2; nj2++) {
            int r0  = bm + wm0 + mi * 16 + (lane >> 2);
            int col = bn + wn0 + nj2 * 8 + (lane & 3) * 2;
            float v0 = acc[mi][nj2][0] * alpha, v1 = acc[mi][nj2][1] * alpha;
            float v2 = acc[mi][nj2][2] * alpha, v3 = acc[mi][nj2][3] * alpha;
            size_t o0 = (size_t)r0 * ldc + col;
            size_t o1 = o0 + (size_t)8 * ldc;
            if (MODE == 1) {
                bf16 h0, l0, h1, l1;
                bf162 ph, pl;
                split2(v0, h0, l0); split2(v1, h1, l1);
                ph.x = h0; ph.y = h1; pl.x = l0; pl.y = l1;
                *(bf162*)&Chi[o0] = ph; *(bf162*)&Clo[o0] = pl;
                split2(v2, h0, l0); split2(v3, h1, l1);
                ph.x = h0; ph.y = h1; pl.x = l0; pl.y = l1;
                *(bf162*)&Chi[o1] = ph; *(bf162*)&Clo[o1] = pl;
            } else if (MODE == 2) {
                float2 ha = *(const float2*)&Hm[o0];
                float2 hb = *(const float2*)&Hm[o1];
                float2 oA = make_float2(ALPHA_C * v0 + (1.f - ALPHA_C) * ha.x,
                                        ALPHA_C * v1 + (1.f - ALPHA_C) * ha.y);
                float2 oB = make_float2(ALPHA_C * v2 + (1.f - ALPHA_C) * hb.x,
                                        ALPHA_C * v3 + (1.f - ALPHA_C) * hb.y);
                *(float2*)&C[o0] = oA;
                *(float2*)&C[o1] = oB;
            } else {
                if (bias) {
                    float b0 = bias[col], b1 = bias[col + 1];
                    v0 += b0; v1 += b1; v2 += b0; v3 += b1;
                }
                *(float2*)&C[o0] = make_float2(v0, v1);
                *(float2*)&C[o1] = make_float2(v2, v3);
            }
        }
    }
}

// ---------------- fused mix_pre + softmax + mix_post ----------------
// 1 CTA per row i, 512 threads. Reads blended [h][i][j] (from d_out),
// stages mixed dots in 131KB dynamic smem, writes attn as bf16 hi/lo
// at interleaved [i][g][j].
__global__ void __launch_bounds__(512)
fused_softmax(const float* __restrict__ blended,
              const float* __restrict__ mpre, const float* __restrict__ mpost,
              bf16* __restrict__ ath, bf16* __restrict__ atl)
{
    extern __shared__ float sd[];                 // [16][2048]
    __shared__ float smixA[HEADS * HEADS], smixB[HEADS * HEADS];
    __shared__ float redm[16][HEADS], redl[16][HEADS];
    __shared__ float fm[HEADS], fl[HEADS];

    const int i = blockIdx.x, tid = threadIdx.x;
    if (tid < 256) { smixA[tid] = mpre[tid]; smixB[tid] = mpost[tid]; }
    __syncthreads();

    const size_t sH = (size_t)N_TOK * N_TOK;
    const size_t hbase = (size_t)i * N_TOK;
    const int j = tid * 4;

    // ---- pass A: blend rows -> mix_pre -> smem, online stats ----
    float4 bl4[HEADS];
#pragma unroll
    for (int h = 0; h < HEADS; h++)
        bl4[h] = *(const float4*)&blended[(size_t)h * sH + hbase + j];

    float m[HEADS], l[HEADS];
#pragma unroll
    for (int g = 0; g < HEADS; g++) {
        float4 d = make_float4(0.f, 0.f, 0.f, 0.f);
#pragma unroll
        for (int h = 0; h < HEADS; h++) {
            float w = smixA[h * HEADS + g];
            d.x += bl4[h].x * w; d.y += bl4[h].y * w;
            d.z += bl4[h].z * w; d.w += bl4[h].w * w;
        }
        *(float4*)&sd[g * N_TOK + j] = d;
        float mx = fmaxf(fmaxf(d.x, d.y), fmaxf(d.z, d.w));
        m[g] = mx;
        l[g] = __expf(d.x - mx) + __expf(d.y - mx)
             + __expf(d.z - mx) + __expf(d.w - mx);
    }

    // ---- stats reduction (512 threads = 16 warps) ----
#pragma unroll
    for (int g = 0; g < HEADS; g++) {
        for (int o = 16; o > 0; o >>= 1) {
            float m2 = __shfl_xor_sync(0xffffffffu, m[g], o);
            float l2 = __shfl_xor_sync(0xffffffffu, l[g], o);
            float nm = fmaxf(m[g], m2);
            l[g] = l[g] * __expf(m[g] - nm) + l2 * __expf(m2 - nm);
            m[g] = nm;
        }
    }
    int warp = tid >> 5, lane = tid & 31;
    if (lane == 0) {
#pragma unroll
        for (int g = 0; g < HEADS; g++) { redm[warp][g] = m[g]; redl[warp][g] = l[g]; }
    }
    __syncthreads();
    if (tid < HEADS) {
        int g = tid;
        float M = redm[0][g], L = redl[0][g];
#pragma unroll
        for (int w = 1; w < 16; w++) {
            float m2 = redm[w][g], l2 = redl[w][g];
            float nm = fmaxf(M, m2);
            L = L * __expf(M - nm) + l2 * __expf(m2 - nm);
            M = nm;
        }
        fm[g] = M; fl[g] = 1.0f / L;
    }
    __syncthreads();

    // ---- pass B: normalize + mix_post + split ----
    float4 p4[HEADS];
#pragma unroll
    for (int h = 0; h < HEADS; h++) {
        float mh = fm[h], li = fl[h];
        float4 d = *(const float4*)&sd[h * N_TOK + j];
        p4[h].x = __expf(d.x - mh) * li;
        p4[h].y = __expf(d.y - mh) * li;
        p4[h].z = __expf(d.z - mh) * li;
        p4[h].w = __expf(d.w - mh) * li;
    }
    const size_t rbase = (size_t)i * (HEADS * N_TOK);
#pragma unroll
    for (int g = 0; g < HEADS; g++) {
        float4 a = make_float4(0.f, 0.f, 0.f, 0.f);
#pragma unroll
        for (int h = 0; h < HEADS; h++) {
            float w = smixB[h * HEADS + g];
            a.x += p4[h].x * w; a.y += p4[h].y * w;
            a.z += p4[h].z * w; a.w += p4[h].w * w;
        }
        bf16 h0, l0, h1, l1;
        bf162 ph, pl;
        size_t o = rbase + g * N_TOK + j;
        split2(a.x, h0, l0); split2(a.y, h1, l1);
        ph.x = h0; ph.y = h1; pl.x = l0; pl.y = l1;
        ((bf162*)&ath[o])[0] = ph; ((bf162*)&atl[o])[0] = pl;
        split2(a.z, h0, l0); split2(a.w, h1, l1);
        ph.x = h0; ph.y = h1; pl.x = l0; pl.y = l1;
        ((bf162*)&ath[o])[1] = ph; ((bf162*)&atl[o])[1] = pl;
    }
}

// ---------------- launch ----------------
extern "C" void kernel_launch(void* const* d_in, const int* in_sizes, int n_in,
                              void* d_out, int out_size)
{
    const float* x        = (const float*)d_in[0];
    const float* h_in     = (const float*)d_in[1];
    const float* ln_g     = (const float*)d_in[2];
    const float* ln_b     = (const float*)d_in[3];
    const float* Wq       = (const float*)d_in[4];
    const float* Wkv      = (const float*)d_in[5];
    const float* mix_pre  = (const float*)d_in[6];
    const float* mix_post = (const float*)d_in[7];
    const float* Wout     = (const float*)d_in[8];
    const float* bout     = (const float*)d_in[9];

    float* out = (float*)d_out;
    float* blended_out = out + (size_t)N_TOK * DIMX;

    float* c12;
    bf16 *xnh, *xnl, *wqkvh, *wqkvl, *woh, *wol;
    bf16 *qh, *ql, *kh, *kl, *vth, *vtl, *ath, *atl, *aoh, *aol;
    cudaGetSymbolAddress((void**)&c12,  g_c12);
    cudaGetSymbolAddress((void**)&xnh,  g_xnh);
    cudaGetSymbolAddress((void**)&xnl,  g_xnl);
    cudaGetSymbolAddress((void**)&wqkvh, g_wqkvh);
    cudaGetSymbolAddress((void**)&wqkvl, g_wqkvl);
    cudaGetSymbolAddress((void**)&woh,  g_woh);
    cudaGetSymbolAddress((void**)&wol,  g_wol);
    cudaGetSymbolAddress((void**)&qh,   g_qh);
    cudaGetSymbolAddress((void**)&ql,   g_ql);
    cudaGetSymbolAddress((void**)&kh,   g_kh);
    cudaGetSymbolAddress((void**)&kl,   g_kl);
    cudaGetSymbolAddress((void**)&vth,  g_vth);
    cudaGetSymbolAddress((void**)&vtl,  g_vtl);
    cudaGetSymbolAddress((void**)&ath,  g_ath);
    cudaGetSymbolAddress((void**)&atl,  g_atl);
    cudaGetSymbolAddress((void**)&aoh,  g_aoh);
    cudaGetSymbolAddress((void**)&aol,  g_aol);

    const int SM_BIG = (2 * 128 + 2 * 128) * 64 * 2 * 2;  // 131072 B
    const int SM_AV  = (2 * 128 + 2 * 64)  * 64 * 2 * 2;  //  98304 B
    const int SM_SOFT = HEADS * N_TOK * 4;                // 131072 B
    cudaFuncSetAttribute(gemm_bf3<128, 128, 64, 32, 0>,
                         cudaFuncAttributeMaxDynamicSharedMemorySize, SM_BIG);
    cudaFuncSetAttribute(gemm_bf3<128, 128, 64, 32, 2>,
                         cudaFuncAttributeMaxDynamicSharedMemorySize, SM_BIG);
    cudaFuncSetAttribute(gemm_bf3<128, 64, 32, 32, 1>,
                         cudaFuncAttributeMaxDynamicSharedMemorySize, SM_AV);
    cudaFuncSetAttribute(fused_softmax,
                         cudaFuncAttributeMaxDynamicSharedMemorySize, SM_SOFT);

    // 1. layernorm + split
    ln_split_kernel<<<N_TOK, 256>>>(x, ln_g, ln_b, xnh, xnl);

    // 2. weight transposes + split
    tsplit_kernel<<<dim3(32, 32, 1), 256>>>(Wq, INNER, 0, wqkvh, wqkvl, DIMX, 0, DIMX, INNER);
    tsplit_kernel<<<dim3(64, 32, 1), 256>>>(Wkv, 2 * INNER, 0,
                                            wqkvh + (size_t)INNER * DIMX,
                                            wqkvl + (size_t)INNER * DIMX,
                                            DIMX, 0, DIMX, 2 * INNER);
    tsplit_kernel<<<dim3(32, 32, 1), 256>>>(Wout, DIMX, 0, woh, wol, INNER, 0, INNER, DIMX);

    // 3. c12 = xn @ [Wq|Wkv]
    gemm_bf3<128, 128, 64, 32, 0><<<dim3(NQKV / 128, N_TOK / 128, 1), 256, SM_BIG>>>(
        xnh, xnl, wqkvh, wqkvl, c12, nullptr, nullptr, nullptr,
        DIMX, DIMX, DIMX, NQKV, 0, 0, 0, 1.f, nullptr);

    // 4. remap q/k; 5. v^T per head
    remap_split<<<(N_TOK * INNER + 255) / 256, 256>>>(c12, qh, ql, kh, kl);
    tsplit_kernel<<<dim3(2, 64, HEADS), 256>>>(c12 + 2 * INNER, NQKV, DHEAD,
                                               vth, vtl, N_TOK,
                                               (long long)DHEAD * N_TOK,
                                               N_TOK, DHEAD);

    // 6. blended[h][i][j] = 0.45*SCALE*(q@k^T) + 0.55*h  (fused into epilogue)
    gemm_bf3<128, 128, 64, 32, 2><<<dim3(N_TOK / 128, N_TOK / 128, HEADS), 256, SM_BIG>>>(
        qh, ql, kh, kl, blended_out, nullptr, nullptr, h_in,
        DHEAD, DHEAD, DHEAD, N_TOK,
        (long long)N_TOK * DHEAD, (long long)N_TOK * DHEAD,
        (long long)N_TOK * N_TOK,
        SCALE_C, nullptr);

    // 7. fused mix_pre + softmax + mix_post -> attn bf16 hi/lo [i][g][j]
    fused_softmax<<<N_TOK, 512, SM_SOFT>>>(blended_out, mix_pre, mix_post, ath, atl);

    // 8. ao = attn @ v
    gemm_bf3<128, 64, 32, 32, 1><<<dim3(1, N_TOK / 128, HEADS), 256, SM_AV>>>(
        ath, atl, vth, vtl, nullptr, aoh, aol, nullptr,
        N_TOK, HEADS * N_TOK, N_TOK, INNER,
        (long long)N_TOK, (long long)DHEAD * N_TOK, (long long)DHEAD,
        1.f, nullptr);

    // 9. out = ao @ Wout + bout
    gemm_bf3<128, 128, 64, 32, 0><<<dim3(DIMX / 128, N_TOK / 128, 1), 256, SM_BIG>>>(
        aoh, aol, woh, wol, out, nullptr, nullptr, nullptr,
        INNER, INNER, INNER, DIMX, 0, 0, 0, 1.f, bout);

    (void)in_sizes; (void)n_in; (void)out_size;
}

// round 6
// speedup vs baseline: 5.6193x; 1.0724x over previous
#include <cuda_runtime.h>
#include <cuda_bf16.h>
#include <math.h>
#include <stdint.h>

#define N_TOK 2048
#define DIMX  1024
#define HEADS 16
#define DHEAD 64
#define INNER 1024
#define NQKV  3072
#define ALPHA_C 0.45f
#define SCALE_C 0.125f

typedef __nv_bfloat16 bf16;
typedef __nv_bfloat162 bf162;

// ---------------- device buffers ----------------
__device__ __align__(256) float g_c12[(size_t)N_TOK * NQKV];
__device__ __align__(256) bf16  g_xnh[(size_t)N_TOK * DIMX];
__device__ __align__(256) bf16  g_xnl[(size_t)N_TOK * DIMX];
__device__ __align__(256) bf16  g_wqkvh[(size_t)NQKV * DIMX];
__device__ __align__(256) bf16  g_wqkvl[(size_t)NQKV * DIMX];
__device__ __align__(256) bf16  g_woh[(size_t)DIMX * INNER];
__device__ __align__(256) bf16  g_wol[(size_t)DIMX * INNER];
__device__ __align__(256) bf16  g_qh[(size_t)HEADS * N_TOK * DHEAD];
__device__ __align__(256) bf16  g_ql[(size_t)HEADS * N_TOK * DHEAD];
__device__ __align__(256) bf16  g_kh[(size_t)HEADS * N_TOK * DHEAD];
__device__ __align__(256) bf16  g_kl[(size_t)HEADS * N_TOK * DHEAD];
__device__ __align__(256) bf16  g_vth[(size_t)HEADS * DHEAD * N_TOK];
__device__ __align__(256) bf16  g_vtl[(size_t)HEADS * DHEAD * N_TOK];
__device__ __align__(256) bf16  g_ath[(size_t)HEADS * N_TOK * N_TOK];
__device__ __align__(256) bf16  g_atl[(size_t)HEADS * N_TOK * N_TOK];
__device__ __align__(256) bf16  g_aoh[(size_t)N_TOK * INNER];
__device__ __align__(256) bf16  g_aol[(size_t)N_TOK * INNER];

// ---------------- helpers ----------------
__device__ __forceinline__ uint32_t s2u(const void* p) {
    return (uint32_t)__cvta_generic_to_shared(p);
}
__device__ __forceinline__ void cp16(uint32_t d, const void* g) {
    asm volatile("cp.async.cg.shared.global [%0],[%1],16;" :: "r"(d), "l"(g));
}
__device__ __forceinline__ void cpcommit() { asm volatile("cp.async.commit_group;"); }
template<int Nw> __device__ __forceinline__ void cpwait() {
    asm volatile("cp.async.wait_group %0;" :: "n"(Nw));
}
__device__ __forceinline__ void ldsm4(uint32_t* r, uint32_t addr) {
    asm volatile("ldmatrix.sync.aligned.m8n8.x4.shared.b16 {%0,%1,%2,%3},[%4];"
                 : "=r"(r[0]), "=r"(r[1]), "=r"(r[2]), "=r"(r[3]) : "r"(addr));
}
__device__ __forceinline__ void mma_bf(float* d, const uint32_t* a, uint32_t b0, uint32_t b1) {
    asm volatile(
        "mma.sync.aligned.m16n8k16.row.col.f32.bf16.bf16.f32 "
        "{%0,%1,%2,%3},{%4,%5,%6,%7},{%8,%9},{%0,%1,%2,%3};"
        : "+f"(d[0]), "+f"(d[1]), "+f"(d[2]), "+f"(d[3])
        : "r"(a[0]), "r"(a[1]), "r"(a[2]), "r"(a[3]), "r"(b0), "r"(b1));
}
__device__ __forceinline__ void split2(float v, bf16& h, bf16& l) {
    h = __float2bfloat16(v);
    l = __float2bfloat16(v - __bfloat162float(h));
}

// ---------------- layernorm + split ----------------
__global__ void ln_split_kernel(const float* __restrict__ x,
                                const float* __restrict__ gam,
                                const float* __restrict__ bet,
                                bf16* __restrict__ oh, bf16* __restrict__ ol)
{
    int row = blockIdx.x;
    const float* xr = x + (size_t)row * DIMX;
    float s = 0.f, s2 = 0.f;
    for (int c = threadIdx.x; c < DIMX; c += blockDim.x) {
        float v = xr[c];
        s += v; s2 += v * v;
    }
    __shared__ float red[64];
    for (int o = 16; o > 0; o >>= 1) {
        s  += __shfl_xor_sync(0xffffffffu, s,  o);
        s2 += __shfl_xor_sync(0xffffffffu, s2, o);
    }
    int warp = threadIdx.x >> 5, lane = threadIdx.x & 31;
    int nwarp = blockDim.x >> 5;
    if (lane == 0) { red[warp] = s; red[warp + 32] = s2; }
    __syncthreads();
    if (warp == 0) {
        s  = (lane < nwarp) ? red[lane] : 0.f;
        s2 = (lane < nwarp) ? red[lane + 32] : 0.f;
        for (int o = 16; o > 0; o >>= 1) {
            s  += __shfl_xor_sync(0xffffffffu, s,  o);
            s2 += __shfl_xor_sync(0xffffffffu, s2, o);
        }
        if (lane == 0) { red[0] = s; red[1] = s2; }
    }
    __syncthreads();
    float mean = red[0] * (1.f / DIMX);
    float var  = red[1] * (1.f / DIMX) - mean * mean;
    float inv  = rsqrtf(var + 1e-5f);
    for (int c = threadIdx.x; c < DIMX; c += blockDim.x) {
        float y = (xr[c] - mean) * inv * gam[c] + bet[c];
        bf16 h, l; split2(y, h, l);
        oh[(size_t)row * DIMX + c] = h;
        ol[(size_t)row * DIMX + c] = l;
    }
}

// ---------------- transpose + split ----------------
__global__ void tsplit_kernel(const float* __restrict__ in, int ldin, long long sIn,
                              bf16* __restrict__ oh, bf16* __restrict__ ol,
                              int ldout, long long sOut, int R, int C)
{
    __shared__ float t[32][33];
    in += (size_t)blockIdx.z * sIn;
    oh += (size_t)blockIdx.z * sOut;
    ol += (size_t)blockIdx.z * sOut;
    int r0 = blockIdx.y * 32, c0 = blockIdx.x * 32;
    int tx = threadIdx.x & 31, ty = threadIdx.x >> 5;
#pragma unroll
    for (int i = 0; i < 32; i += 8) {
        int r = r0 + ty + i;
        if (r < R && c0 + tx < C) t[ty + i][tx] = in[(size_t)r * ldin + c0 + tx];
    }
    __syncthreads();
#pragma unroll
    for (int i = 0; i < 32; i += 8) {
        int c = c0 + ty + i, r = r0 + tx;
        if (c < C && r < R) {
            float v = t[tx][ty + i];
            bf16 h, l; split2(v, h, l);
            oh[(size_t)c * ldout + r] = h;
            ol[(size_t)c * ldout + r] = l;
        }
    }
}

// ---------------- remap + split ----------------
__global__ void remap_split(const float* __restrict__ c12,
                            bf16* __restrict__ qh, bf16* __restrict__ ql,
                            bf16* __restrict__ kh, bf16* __restrict__ kl)
{
    int idx = blockIdx.x * blockDim.x + threadIdx.x;
    if (idx >= N_TOK * INNER) return;
    int i = idx >> 10, col = idx & 1023;
    int h = col >> 6, d = col & 63;
    float qv = c12[(size_t)i * NQKV + col];
    float kv = c12[(size_t)i * NQKV + INNER + col];
    size_t dst = ((size_t)h * N_TOK + i) * DHEAD + d;
    bf16 a, b;
    split2(qv, a, b); qh[dst] = a; ql[dst] = b;
    split2(kv, a, b); kh[dst] = a; kl[dst] = b;
}

// ---------------- bf16x3 tensor-core GEMM (mma.sync HMMA) ----------------
// MODE 0: C fp32 (+bias). MODE 1: split to Chi/Clo bf16. MODE 2: blend —
// C = ALPHA*alpha*acc + (1-ALPHA)*Hm, same layout as C.
// Launch smem: min(K/64, 2) * SS * 2 bytes.
template<int BM, int BN, int WM, int WN, int MODE>
__global__ void __launch_bounds__(256, 2)
gemm_bf3(const bf16* __restrict__ Ahi, const bf16* __restrict__ Alo,
         const bf16* __restrict__ Bhi, const bf16* __restrict__ Blo,
         float* __restrict__ C, bf16* __restrict__ Chi, bf16* __restrict__ Clo,
         const float* __restrict__ Hm,
         int K, int lda, int ldb, int ldc,
         long long sA, long long sB, long long sC,
         float alpha, const float* __restrict__ bias)
{
    constexpr int MI  = WM / 16;
    constexpr int NJ  = WN / 16;
    constexpr int NJ2 = WN / 8;
    constexpr int NA  = BM * 8 / 256;
    constexpr int NB  = BN * 8 / 256;
    constexpr int SS  = (2 * BM + 2 * BN) * 64;
    constexpr int WNN = BN / WN;

    extern __shared__ bf16 sm[];

    Ahi += (size_t)blockIdx.z * sA;  Alo += (size_t)blockIdx.z * sA;
    Bhi += (size_t)blockIdx.z * sB;  Blo += (size_t)blockIdx.z * sB;
    if (MODE == 1) { Chi += (size_t)blockIdx.z * sC; Clo += (size_t)blockIdx.z * sC; }
    else           { C   += (size_t)blockIdx.z * sC; }
    if (MODE == 2) { Hm  += (size_t)blockIdx.z * sC; }

    const int bm = blockIdx.y * BM, bn = blockIdx.x * BN;
    const int tid = threadIdx.x, lane = tid & 31, wid = tid >> 5;
    const int wm0 = (wid / WNN) * WM, wn0 = (wid % WNN) * WN;

    float acc[MI][NJ2][4];
#pragma unroll
    for (int i = 0; i < MI; i++)
#pragma unroll
        for (int j = 0; j < NJ2; j++) {
            acc[i][j][0] = 0.f; acc[i][j][1] = 0.f;
            acc[i][j][2] = 0.f; acc[i][j][3] = 0.f;
        }

    auto issue = [&](int kt, int stg) {
        bf16* sA_hi = sm + stg * SS;
        bf16* sA_lo = sA_hi + BM * 64;
        bf16* sB_hi = sA_lo + BM * 64;
        bf16* sB_lo = sB_hi + BN * 64;
#pragma unroll
        for (int i = 0; i < NA; i++) {
            int id = tid + i * 256, r = id >> 3, c = id & 7;
            size_t go = (size_t)(bm + r) * lda + kt * 64 + c * 8;
            int so = r * 64 + ((c ^ (r & 7)) << 3);
            cp16(s2u(sA_hi + so), Ahi + go);
            cp16(s2u(sA_lo + so), Alo + go);
        }
#pragma unroll
        for (int i = 0; i < NB; i++) {
            int id = tid + i * 256, r = id >> 3, c = id & 7;
            size_t go = (size_t)(bn + r) * ldb + kt * 64 + c * 8;
            int so = r * 64 + ((c ^ (r & 7)) << 3);
            cp16(s2u(sB_hi + so), Bhi + go);
            cp16(s2u(sB_lo + so), Blo + go);
        }
    };

    const int KT = K >> 6;
    issue(0, 0); cpcommit();

    for (int kt = 0; kt < KT; kt++) {
        int cur = kt & 1;
        if (kt + 1 < KT) { issue(kt + 1, cur ^ 1); cpcommit(); cpwait<1>(); }
        else             { cpwait<0>(); }
        __syncthreads();

        const bf16* sA_hi = sm + cur * SS;
        const bf16* sA_lo = sA_hi + BM * 64;
        const bf16* sB_hi = sA_lo + BM * 64;
        const bf16* sB_lo = sB_hi + BN * 64;

#pragma unroll
        for (int s = 0; s < 4; s++) {
            const int c0 = 2 * s;
            uint32_t ah[MI][4], al[MI][4];
#pragma unroll
            for (int mi = 0; mi < MI; mi++) {
                int row = wm0 + mi * 16 + (lane & 15);
                int ch  = c0 + (lane >> 4);
                int off = row * 64 + ((ch ^ (row & 7)) << 3);
                ldsm4(ah[mi], s2u(sA_hi + off));
                ldsm4(al[mi], s2u(sA_lo + off));
            }
#pragma unroll
            for (int nj = 0; nj < NJ; nj++) {
                uint32_t bh[4], bl[4];
                int rowb = wn0 + nj * 16 + (lane & 15);
                int ch   = c0 + (lane >> 4);
                int off  = rowb * 64 + ((ch ^ (rowb & 7)) << 3);
                ldsm4(bh, s2u(sB_hi + off));
                ldsm4(bl, s2u(sB_lo + off));
#pragma unroll
                for (int mi = 0; mi < MI; mi++) {
                    mma_bf(acc[mi][2 * nj],     ah[mi], bh[0], bh[2]);
                    mma_bf(acc[mi][2 * nj],     ah[mi], bl[0], bl[2]);
                    mma_bf(acc[mi][2 * nj],     al[mi], bh[0], bh[2]);
                    mma_bf(acc[mi][2 * nj + 1], ah[mi], bh[1], bh[3]);
                    mma_bf(acc[mi][2 * nj + 1], ah[mi], bl[1], bl[3]);
                    mma_bf(acc[mi][2 * nj + 1], al[mi], bh[1], bh[3]);
                }
            }
        }
        __syncthreads();
    }

    // ---- epilogue ----
#pragma unroll
    for (int mi = 0; mi < MI; mi++) {
#pragma unroll
        for (int nj2 = 0; nj2 < NJ2; nj2++) {
            int r0  = bm + wm0 + mi * 16 + (lane >> 2);
            int col = bn + wn0 + nj2 * 8 + (lane & 3) * 2;
            float v0 = acc[mi][nj2][0] * alpha, v1 = acc[mi][nj2][1] * alpha;
            float v2 = acc[mi][nj2][2] * alpha, v3 = acc[mi][nj2][3] * alpha;
            size_t o0 = (size_t)r0 * ldc + col;
            size_t o1 = o0 + (size_t)8 * ldc;
            if (MODE == 1) {
                bf16 h0, l0, h1, l1;
                bf162 ph, pl;
                split2(v0, h0, l0); split2(v1, h1, l1);
                ph.x = h0; ph.y = h1; pl.x = l0; pl.y = l1;
                *(bf162*)&Chi[o0] = ph; *(bf162*)&Clo[o0] = pl;
                split2(v2, h0, l0); split2(v3, h1, l1);
                ph.x = h0; ph.y = h1; pl.x = l0; pl.y = l1;
                *(bf162*)&Chi[o1] = ph; *(bf162*)&Clo[o1] = pl;
            } else if (MODE == 2) {
                float2 ha = *(const float2*)&Hm[o0];
                float2 hb = *(const float2*)&Hm[o1];
                float2 oA = make_float2(ALPHA_C * v0 + (1.f - ALPHA_C) * ha.x,
                                        ALPHA_C * v1 + (1.f - ALPHA_C) * ha.y);
                float2 oB = make_float2(ALPHA_C * v2 + (1.f - ALPHA_C) * hb.x,
                                        ALPHA_C * v3 + (1.f - ALPHA_C) * hb.y);
                *(float2*)&C[o0] = oA;
                *(float2*)&C[o1] = oB;
            } else {
                if (bias) {
                    float b0 = bias[col], b1 = bias[col + 1];
                    v0 += b0; v1 += b1; v2 += b0; v3 += b1;
                }
                *(float2*)&C[o0] = make_float2(v0, v1);
                *(float2*)&C[o1] = make_float2(v2, v3);
            }
        }
    }
}

// ---------------- fused mix_pre + softmax + mix_post ----------------
__global__ void __launch_bounds__(512)
fused_softmax(const float* __restrict__ blended,
              const float* __restrict__ mpre, const float* __restrict__ mpost,
              bf16* __restrict__ ath, bf16* __restrict__ atl)
{
    extern __shared__ float sd[];
    __shared__ float smixA[HEADS * HEADS], smixB[HEADS * HEADS];
    __shared__ float redm[16][HEADS], redl[16][HEADS];
    __shared__ float fm[HEADS], fl[HEADS];

    const int i = blockIdx.x, tid = threadIdx.x;
    if (tid < 256) { smixA[tid] = mpre[tid]; smixB[tid] = mpost[tid]; }
    __syncthreads();

    const size_t sH = (size_t)N_TOK * N_TOK;
    const size_t hbase = (size_t)i * N_TOK;
    const int j = tid * 4;

    float4 bl4[HEADS];
#pragma unroll
    for (int h = 0; h < HEADS; h++)
        bl4[h] = *(const float4*)&blended[(size_t)h * sH + hbase + j];

    float m[HEADS], l[HEADS];
#pragma unroll
    for (int g = 0; g < HEADS; g++) {
        float4 d = make_float4(0.f, 0.f, 0.f, 0.f);
#pragma unroll
        for (int h = 0; h < HEADS; h++) {
            float w = smixA[h * HEADS + g];
            d.x += bl4[h].x * w; d.y += bl4[h].y * w;
            d.z += bl4[h].z * w; d.w += bl4[h].w * w;
        }
        *(float4*)&sd[g * N_TOK + j] = d;
        float mx = fmaxf(fmaxf(d.x, d.y), fmaxf(d.z, d.w));
        m[g] = mx;
        l[g] = __expf(d.x - mx) + __expf(d.y - mx)
             + __expf(d.z - mx) + __expf(d.w - mx);
    }

#pragma unroll
    for (int g = 0; g < HEADS; g++) {
        for (int o = 16; o > 0; o >>= 1) {
            float m2 = __shfl_xor_sync(0xffffffffu, m[g], o);
            float l2 = __shfl_xor_sync(0xffffffffu, l[g], o);
            float nm = fmaxf(m[g], m2);
            l[g] = l[g] * __expf(m[g] - nm) + l2 * __expf(m2 - nm);
            m[g] = nm;
        }
    }
    int warp = tid >> 5, lane = tid & 31;
    if (lane == 0) {
#pragma unroll
        for (int g = 0; g < HEADS; g++) { redm[warp][g] = m[g]; redl[warp][g] = l[g]; }
    }
    __syncthreads();
    if (tid < HEADS) {
        int g = tid;
        float M = redm[0][g], L = redl[0][g];
#pragma unroll
        for (int w = 1; w < 16; w++) {
            float m2 = redm[w][g], l2 = redl[w][g];
            float nm = fmaxf(M, m2);
            L = L * __expf(M - nm) + l2 * __expf(m2 - nm);
            M = nm;
        }
        fm[g] = M; fl[g] = 1.0f / L;
    }
    __syncthreads();

    float4 p4[HEADS];
#pragma unroll
    for (int h = 0; h < HEADS; h++) {
        float mh = fm[h], li = fl[h];
        float4 d = *(const float4*)&sd[h * N_TOK + j];
        p4[h].x = __expf(d.x - mh) * li;
        p4[h].y = __expf(d.y - mh) * li;
        p4[h].z = __expf(d.z - mh) * li;
        p4[h].w = __expf(d.w - mh) * li;
    }
    const size_t rbase = (size_t)i * (HEADS * N_TOK);
#pragma unroll
    for (int g = 0; g < HEADS; g++) {
        float4 a = make_float4(0.f, 0.f, 0.f, 0.f);
#pragma unroll
        for (int h = 0; h < HEADS; h++) {
            float w = smixB[h * HEADS + g];
            a.x += p4[h].x * w; a.y += p4[h].y * w;
            a.z += p4[h].z * w; a.w += p4[h].w * w;
        }
        bf16 h0, l0, h1, l1;
        bf162 ph2, pl2;
        size_t o = rbase + g * N_TOK + j;
        split2(a.x, h0, l0); split2(a.y, h1, l1);
        ph2.x = h0; ph2.y = h1; pl2.x = l0; pl2.y = l1;
        ((bf162*)&ath[o])[0] = ph2; ((bf162*)&atl[o])[0] = pl2;
        split2(a.z, h0, l0); split2(a.w, h1, l1);
        ph2.x = h0; ph2.y = h1; pl2.x = l0; pl2.y = l1;
        ((bf162*)&ath[o])[1] = ph2; ((bf162*)&atl[o])[1] = pl2;
    }
}

// ---------------- launch ----------------
extern "C" void kernel_launch(void* const* d_in, const int* in_sizes, int n_in,
                              void* d_out, int out_size)
{
    const float* x        = (const float*)d_in[0];
    const float* h_in     = (const float*)d_in[1];
    const float* ln_g     = (const float*)d_in[2];
    const float* ln_b     = (const float*)d_in[3];
    const float* Wq       = (const float*)d_in[4];
    const float* Wkv      = (const float*)d_in[5];
    const float* mix_pre  = (const float*)d_in[6];
    const float* mix_post = (const float*)d_in[7];
    const float* Wout     = (const float*)d_in[8];
    const float* bout     = (const float*)d_in[9];

    float* out = (float*)d_out;
    float* blended_out = out + (size_t)N_TOK * DIMX;

    float* c12;
    bf16 *xnh, *xnl, *wqkvh, *wqkvl, *woh, *wol;
    bf16 *qh, *ql, *kh, *kl, *vth, *vtl, *ath, *atl, *aoh, *aol;
    cudaGetSymbolAddress((void**)&c12,  g_c12);
    cudaGetSymbolAddress((void**)&xnh,  g_xnh);
    cudaGetSymbolAddress((void**)&xnl,  g_xnl);
    cudaGetSymbolAddress((void**)&wqkvh, g_wqkvh);
    cudaGetSymbolAddress((void**)&wqkvl, g_wqkvl);
    cudaGetSymbolAddress((void**)&woh,  g_woh);
    cudaGetSymbolAddress((void**)&wol,  g_wol);
    cudaGetSymbolAddress((void**)&qh,   g_qh);
    cudaGetSymbolAddress((void**)&ql,   g_ql);
    cudaGetSymbolAddress((void**)&kh,   g_kh);
    cudaGetSymbolAddress((void**)&kl,   g_kl);
    cudaGetSymbolAddress((void**)&vth,  g_vth);
    cudaGetSymbolAddress((void**)&vtl,  g_vtl);
    cudaGetSymbolAddress((void**)&ath,  g_ath);
    cudaGetSymbolAddress((void**)&atl,  g_atl);
    cudaGetSymbolAddress((void**)&aoh,  g_aoh);
    cudaGetSymbolAddress((void**)&aol,  g_aol);

    // BN=64 tiles: per-stage smem = (2*128 + 2*64)*64 halves = 48KB
    const int SM_2STG = 2 * 49152;   // 98304 (K > 64)
    const int SM_1STG = 49152;       // QK^T (K = 64 -> KT = 1)
    const int SM_SOFT = HEADS * N_TOK * 4;   // 131072
    cudaFuncSetAttribute(gemm_bf3<128, 64, 32, 32, 0>,
                         cudaFuncAttributeMaxDynamicSharedMemorySize, SM_2STG);
    cudaFuncSetAttribute(gemm_bf3<128, 64, 32, 32, 2>,
                         cudaFuncAttributeMaxDynamicSharedMemorySize, SM_2STG);
    cudaFuncSetAttribute(gemm_bf3<128, 64, 32, 32, 1>,
                         cudaFuncAttributeMaxDynamicSharedMemorySize, SM_2STG);
    cudaFuncSetAttribute(fused_softmax,
                         cudaFuncAttributeMaxDynamicSharedMemorySize, SM_SOFT);

    // 1. layernorm + split
    ln_split_kernel<<<N_TOK, 256>>>(x, ln_g, ln_b, xnh, xnl);

    // 2. weight transposes + split
    tsplit_kernel<<<dim3(32, 32, 1), 256>>>(Wq, INNER, 0, wqkvh, wqkvl, DIMX, 0, DIMX, INNER);
    tsplit_kernel<<<dim3(64, 32, 1), 256>>>(Wkv, 2 * INNER, 0,
                                            wqkvh + (size_t)INNER * DIMX,
                                            wqkvl + (size_t)INNER * DIMX,
                                            DIMX, 0, DIMX, 2 * INNER);
    tsplit_kernel<<<dim3(32, 32, 1), 256>>>(Wout, DIMX, 0, woh, wol, INNER, 0, INNER, DIMX);

    // 3. c12 = xn @ [Wq|Wkv]   (M=2048, N=3072, K=1024)
    gemm_bf3<128, 64, 32, 32, 0><<<dim3(NQKV / 64, N_TOK / 128, 1), 256, SM_2STG>>>(
        xnh, xnl, wqkvh, wqkvl, c12, nullptr, nullptr, nullptr,
        DIMX, DIMX, DIMX, NQKV, 0, 0, 0, 1.f, nullptr);

    // 4. remap q/k; 5. v^T per head
    remap_split<<<(N_TOK * INNER + 255) / 256, 256>>>(c12, qh, ql, kh, kl);
    tsplit_kernel<<<dim3(2, 64, HEADS), 256>>>(c12 + 2 * INNER, NQKV, DHEAD,
                                               vth, vtl, N_TOK,
                                               (long long)DHEAD * N_TOK,
                                               N_TOK, DHEAD);

    // 6. blended[h][i][j] = 0.45*SCALE*(q@k^T) + 0.55*h  (epilogue blend)
    gemm_bf3<128, 64, 32, 32, 2><<<dim3(N_TOK / 64, N_TOK / 128, HEADS), 256, SM_1STG>>>(
        qh, ql, kh, kl, blended_out, nullptr, nullptr, h_in,
        DHEAD, DHEAD, DHEAD, N_TOK,
        (long long)N_TOK * DHEAD, (long long)N_TOK * DHEAD,
        (long long)N_TOK * N_TOK,
        SCALE_C, nullptr);

    // 7. fused mix_pre + softmax + mix_post -> attn bf16 hi/lo [i][g][j]
    fused_softmax<<<N_TOK, 512, SM_SOFT>>>(blended_out, mix_pre, mix_post, ath, atl);

    // 8. ao = attn @ v  (per head; M=2048, N=64, K=2048)
    gemm_bf3<128, 64, 32, 32, 1><<<dim3(1, N_TOK / 128, HEADS), 256, SM_2STG>>>(
        ath, atl, vth, vtl, nullptr, aoh, aol, nullptr,
        N_TOK, HEADS * N_TOK, N_TOK, INNER,
        (long long)N_TOK, (long long)DHEAD * N_TOK, (long long)DHEAD,
        1.f, nullptr);

    // 9. out = ao @ Wout + bout  (M=2048, N=1024, K=1024)
    gemm_bf3<128, 64, 32, 32, 0><<<dim3(DIMX / 64, N_TOK / 128, 1), 256, SM_2STG>>>(
        aoh, aol, woh, wol, out, nullptr, nullptr, nullptr,
        INNER, INNER, INNER, DIMX, 0, 0, 0, 1.f, bout);

    (void)in_sizes; (void)n_in; (void)out_size;
}

// round 7
// speedup vs baseline: 6.5667x; 1.1686x over previous
#include <cuda_runtime.h>
#include <cuda_fp16.h>
#include <math.h>
#include <stdint.h>

#define N_TOK 2048
#define DIMX  1024
#define HEADS 16
#define DHEAD 64
#define INNER 1024
#define NQKV  3072
#define ALPHA_C 0.45f
#define SCALE_C 0.125f

typedef __half fp16;

// ---------------- device buffers ----------------
__device__ __align__(256) float g_c12[(size_t)N_TOK * NQKV];
__device__ __align__(256) fp16  g_xnh[(size_t)N_TOK * DIMX];
__device__ __align__(256) fp16  g_xnl[(size_t)N_TOK * DIMX];
__device__ __align__(256) fp16  g_wqkv[(size_t)NQKV * DIMX];
__device__ __align__(256) fp16  g_wo[(size_t)DIMX * INNER];
__device__ __align__(256) fp16  g_qh[(size_t)HEADS * N_TOK * DHEAD];
__device__ __align__(256) fp16  g_ql[(size_t)HEADS * N_TOK * DHEAD];
__device__ __align__(256) fp16  g_k[(size_t)HEADS * N_TOK * DHEAD];
__device__ __align__(256) fp16  g_vt[(size_t)HEADS * DHEAD * N_TOK];
__device__ __align__(256) fp16  g_ath[(size_t)HEADS * N_TOK * N_TOK];
__device__ __align__(256) fp16  g_atl[(size_t)HEADS * N_TOK * N_TOK];
__device__ __align__(256) fp16  g_aoh[(size_t)N_TOK * INNER];
__device__ __align__(256) fp16  g_aol[(size_t)N_TOK * INNER];

// ---------------- helpers ----------------
__device__ __forceinline__ uint32_t s2u(const void* p) {
    return (uint32_t)__cvta_generic_to_shared(p);
}
__device__ __forceinline__ void cp16(uint32_t d, const void* g) {
    asm volatile("cp.async.cg.shared.global [%0],[%1],16;" :: "r"(d), "l"(g));
}
__device__ __forceinline__ void cpcommit() { asm volatile("cp.async.commit_group;"); }
template<int Nw> __device__ __forceinline__ void cpwait() {
    asm volatile("cp.async.wait_group %0;" :: "n"(Nw));
}
__device__ __forceinline__ void ldsm4(uint32_t* r, uint32_t addr) {
    asm volatile("ldmatrix.sync.aligned.m8n8.x4.shared.b16 {%0,%1,%2,%3},[%4];"
                 : "=r"(r[0]), "=r"(r[1]), "=r"(r[2]), "=r"(r[3]) : "r"(addr));
}
__device__ __forceinline__ void mma_f16(float* d, const uint32_t* a, uint32_t b0, uint32_t b1) {
    asm volatile(
        "mma.sync.aligned.m16n8k16.row.col.f32.f16.f16.f32 "
        "{%0,%1,%2,%3},{%4,%5,%6,%7},{%8,%9},{%0,%1,%2,%3};"
        : "+f"(d[0]), "+f"(d[1]), "+f"(d[2]), "+f"(d[3])
        : "r"(a[0]), "r"(a[1]), "r"(a[2]), "r"(a[3]), "r"(b0), "r"(b1));
}
__device__ __forceinline__ void split2h(float v, fp16& h, fp16& l) {
    h = __float2half_rn(v);
    l = __float2half_rn(v - __half2float(h));
}

// ---------------- layernorm + fp16 hi/lo split ----------------
__global__ void ln_split_kernel(const float* __restrict__ x,
                                const float* __restrict__ gam,
                                const float* __restrict__ bet,
                                fp16* __restrict__ oh, fp16* __restrict__ ol)
{
    int row = blockIdx.x;
    const float* xr = x + (size_t)row * DIMX;
    float s = 0.f, s2 = 0.f;
    for (int c = threadIdx.x; c < DIMX; c += blockDim.x) {
        float v = xr[c];
        s += v; s2 += v * v;
    }
    __shared__ float red[64];
    for (int o = 16; o > 0; o >>= 1) {
        s  += __shfl_xor_sync(0xffffffffu, s,  o);
        s2 += __shfl_xor_sync(0xffffffffu, s2, o);
    }
    int warp = threadIdx.x >> 5, lane = threadIdx.x & 31;
    int nwarp = blockDim.x >> 5;
    if (lane == 0) { red[warp] = s; red[warp + 32] = s2; }
    __syncthreads();
    if (warp == 0) {
        s  = (lane < nwarp) ? red[lane] : 0.f;
        s2 = (lane < nwarp) ? red[lane + 32] : 0.f;
        for (int o = 16; o > 0; o >>= 1) {
            s  += __shfl_xor_sync(0xffffffffu, s,  o);
            s2 += __shfl_xor_sync(0xffffffffu, s2, o);
        }
        if (lane == 0) { red[0] = s; red[1] = s2; }
    }
    __syncthreads();
    float mean = red[0] * (1.f / DIMX);
    float var  = red[1] * (1.f / DIMX) - mean * mean;
    float inv  = rsqrtf(var + 1e-5f);
    for (int c = threadIdx.x; c < DIMX; c += blockDim.x) {
        float y = (xr[c] - mean) * inv * gam[c] + bet[c];
        fp16 h, l; split2h(y, h, l);
        oh[(size_t)row * DIMX + c] = h;
        ol[(size_t)row * DIMX + c] = l;
    }
}

// ---------------- transpose to single fp16 ----------------
__global__ void tsingle_kernel(const float* __restrict__ in, int ldin, long long sIn,
                               fp16* __restrict__ o, int ldout, long long sOut,
                               int R, int C)
{
    __shared__ float t[32][33];
    in += (size_t)blockIdx.z * sIn;
    o  += (size_t)blockIdx.z * sOut;
    int r0 = blockIdx.y * 32, c0 = blockIdx.x * 32;
    int tx = threadIdx.x & 31, ty = threadIdx.x >> 5;
#pragma unroll
    for (int i = 0; i < 32; i += 8) {
        int r = r0 + ty + i;
        if (r < R && c0 + tx < C) t[ty + i][tx] = in[(size_t)r * ldin + c0 + tx];
    }
    __syncthreads();
#pragma unroll
    for (int i = 0; i < 32; i += 8) {
        int c = c0 + ty + i, r = r0 + tx;
        if (c < C && r < R)
            o[(size_t)c * ldout + r] = __float2half_rn(t[tx][ty + i]);
    }
}

// ---------------- remap: q -> hi/lo split, k -> single ----------------
__global__ void remap_split(const float* __restrict__ c12,
                            fp16* __restrict__ qh, fp16* __restrict__ ql,
                            fp16* __restrict__ k)
{
    int idx = blockIdx.x * blockDim.x + threadIdx.x;
    if (idx >= N_TOK * INNER) return;
    int i = idx >> 10, col = idx & 1023;
    int h = col >> 6, d = col & 63;
    float qv = c12[(size_t)i * NQKV + col];
    float kv = c12[(size_t)i * NQKV + INNER + col];
    size_t dst = ((size_t)h * N_TOK + i) * DHEAD + d;
    fp16 a, b;
    split2h(qv, a, b); qh[dst] = a; ql[dst] = b;
    k[dst] = __float2half_rn(kv);
}

// ---------------- 2-MMA fp16 tensor-core GEMM ----------------
// C = alpha * (Ahi + Alo) @ B^T. A hi/lo fp16, B single fp16.
// MODE 0: C fp32 (+bias). MODE 1: Chi/Clo fp16 split. MODE 2: blend with Hm.
template<int BM, int BN, int WM, int WN, int MODE>
__global__ void __launch_bounds__(256, 2)
gemm_2m(const fp16* __restrict__ Ahi, const fp16* __restrict__ Alo,
        const fp16* __restrict__ B,
        float* __restrict__ C, fp16* __restrict__ Chi, fp16* __restrict__ Clo,
        const float* __restrict__ Hm,
        int K, int lda, int ldb, int ldc,
        long long sA, long long sB, long long sC,
        float alpha, const float* __restrict__ bias)
{
    constexpr int MI  = WM / 16;
    constexpr int NJ  = WN / 16;
    constexpr int NJ2 = WN / 8;
    constexpr int NAI = BM * 8 / 256;     // A cp16 iters per half
    constexpr int NBI = BN * 8 / 256;     // B cp16 iters
    constexpr int SS  = (2 * BM + BN) * 64;  // halves per stage
    constexpr int WNN = BN / WN;

    extern __shared__ fp16 sm[];

    Ahi += (size_t)blockIdx.z * sA;  Alo += (size_t)blockIdx.z * sA;
    B   += (size_t)blockIdx.z * sB;
    if (MODE == 1) { Chi += (size_t)blockIdx.z * sC; Clo += (size_t)blockIdx.z * sC; }
    else           { C   += (size_t)blockIdx.z * sC; }
    if (MODE == 2) { Hm  += (size_t)blockIdx.z * sC; }

    const int bm = blockIdx.y * BM, bn = blockIdx.x * BN;
    const int tid = threadIdx.x, lane = tid & 31, wid = tid >> 5;
    const int wm0 = (wid / WNN) * WM, wn0 = (wid % WNN) * WN;

    float acc[MI][NJ2][4];
#pragma unroll
    for (int i = 0; i < MI; i++)
#pragma unroll
        for (int j = 0; j < NJ2; j++) {
            acc[i][j][0] = 0.f; acc[i][j][1] = 0.f;
            acc[i][j][2] = 0.f; acc[i][j][3] = 0.f;
        }

    auto issue = [&](int kt, int stg) {
        fp16* sA_hi = sm + stg * SS;
        fp16* sA_lo = sA_hi + BM * 64;
        fp16* sB    = sA_lo + BM * 64;
#pragma unroll
        for (int i = 0; i < NAI; i++) {
            int id = tid + i * 256, r = id >> 3, c = id & 7;
            size_t go = (size_t)(bm + r) * lda + kt * 64 + c * 8;
            int so = r * 64 + ((c ^ (r & 7)) << 3);
            cp16(s2u(sA_hi + so), Ahi + go);
            cp16(s2u(sA_lo + so), Alo + go);
        }
#pragma unroll
        for (int i = 0; i < NBI; i++) {
            int id = tid + i * 256, r = id >> 3, c = id & 7;
            size_t go = (size_t)(bn + r) * ldb + kt * 64 + c * 8;
            int so = r * 64 + ((c ^ (r & 7)) << 3);
            cp16(s2u(sB + so), B + go);
        }
    };

    const int KT = K >> 6;
    issue(0, 0); cpcommit();

    for (int kt = 0; kt < KT; kt++) {
        int cur = kt & 1;
        if (kt + 1 < KT) { issue(kt + 1, cur ^ 1); cpcommit(); cpwait<1>(); }
        else             { cpwait<0>(); }
        __syncthreads();

        const fp16* sA_hi = sm + cur * SS;
        const fp16* sA_lo = sA_hi + BM * 64;
        const fp16* sB    = sA_lo + BM * 64;

#pragma unroll
        for (int s = 0; s < 4; s++) {
            const int c0 = 2 * s;
            uint32_t ah[MI][4], al[MI][4];
#pragma unroll
            for (int mi = 0; mi < MI; mi++) {
                int row = wm0 + mi * 16 + (lane & 15);
                int ch  = c0 + (lane >> 4);
                int off = row * 64 + ((ch ^ (row & 7)) << 3);
                ldsm4(ah[mi], s2u(sA_hi + off));
                ldsm4(al[mi], s2u(sA_lo + off));
            }
#pragma unroll
            for (int nj = 0; nj < NJ; nj++) {
                uint32_t bb[4];
                int rowb = wn0 + nj * 16 + (lane & 15);
                int ch   = c0 + (lane >> 4);
                int off  = rowb * 64 + ((ch ^ (rowb & 7)) << 3);
                ldsm4(bb, s2u(sB + off));
#pragma unroll
                for (int mi = 0; mi < MI; mi++) {
                    mma_f16(acc[mi][2 * nj],     ah[mi], bb[0], bb[2]);
                    mma_f16(acc[mi][2 * nj],     al[mi], bb[0], bb[2]);
                    mma_f16(acc[mi][2 * nj + 1], ah[mi], bb[1], bb[3]);
                    mma_f16(acc[mi][2 * nj + 1], al[mi], bb[1], bb[3]);
                }
            }
        }
        __syncthreads();
    }

    // ---- epilogue ----
#pragma unroll
    for (int mi = 0; mi < MI; mi++) {
#pragma unroll
        for (int nj2 = 0; nj2 < NJ2; nj2++) {
            int r0  = bm + wm0 + mi * 16 + (lane >> 2);
            int col = bn + wn0 + nj2 * 8 + (lane & 3) * 2;
            float v0 = acc[mi][nj2][0] * alpha, v1 = acc[mi][nj2][1] * alpha;
            float v2 = acc[mi][nj2][2] * alpha, v3 = acc[mi][nj2][3] * alpha;
            size_t o0 = (size_t)r0 * ldc + col;
            size_t o1 = o0 + (size_t)8 * ldc;
            if (MODE == 1) {
                fp16 h0, l0, h1, l1;
                __half2 ph, pl;
                split2h(v0, h0, l0); split2h(v1, h1, l1);
                ph = __halves2half2(h0, h1); pl = __halves2half2(l0, l1);
                *(__half2*)&Chi[o0] = ph; *(__half2*)&Clo[o0] = pl;
                split2h(v2, h0, l0); split2h(v3, h1, l1);
                ph = __halves2half2(h0, h1); pl = __halves2half2(l0, l1);
                *(__half2*)&Chi[o1] = ph; *(__half2*)&Clo[o1] = pl;
            } else if (MODE == 2) {
                float2 ha = *(const float2*)&Hm[o0];
                float2 hb = *(const float2*)&Hm[o1];
                *(float2*)&C[o0] = make_float2(ALPHA_C * v0 + (1.f - ALPHA_C) * ha.x,
                                               ALPHA_C * v1 + (1.f - ALPHA_C) * ha.y);
                *(float2*)&C[o1] = make_float2(ALPHA_C * v2 + (1.f - ALPHA_C) * hb.x,
                                               ALPHA_C * v3 + (1.f - ALPHA_C) * hb.y);
            } else {
                if (bias) {
                    float b0 = bias[col], b1 = bias[col + 1];
                    v0 += b0; v1 += b1; v2 += b0; v3 += b1;
                }
                *(float2*)&C[o0] = make_float2(v0, v1);
                *(float2*)&C[o1] = make_float2(v2, v3);
            }
        }
    }
}

// ---------------- fused mix_pre + softmax + mix_post ----------------
__global__ void __launch_bounds__(512)
fused_softmax(const float* __restrict__ blended,
              const float* __restrict__ mpre, const float* __restrict__ mpost,
              fp16* __restrict__ ath, fp16* __restrict__ atl)
{
    extern __shared__ float sd[];
    __shared__ float smixA[HEADS * HEADS], smixB[HEADS * HEADS];
    __shared__ float redm[16][HEADS], redl[16][HEADS];
    __shared__ float fm[HEADS], fl[HEADS];

    const int i = blockIdx.x, tid = threadIdx.x;
    if (tid < 256) { smixA[tid] = mpre[tid]; smixB[tid] = mpost[tid]; }
    __syncthreads();

    const size_t sH = (size_t)N_TOK * N_TOK;
    const size_t hbase = (size_t)i * N_TOK;
    const int j = tid * 4;

    float4 bl4[HEADS];
#pragma unroll
    for (int h = 0; h < HEADS; h++)
        bl4[h] = *(const float4*)&blended[(size_t)h * sH + hbase + j];

    float m[HEADS], l[HEADS];
#pragma unroll
    for (int g = 0; g < HEADS; g++) {
        float4 d = make_float4(0.f, 0.f, 0.f, 0.f);
#pragma unroll
        for (int h = 0; h < HEADS; h++) {
            float w = smixA[h * HEADS + g];
            d.x += bl4[h].x * w; d.y += bl4[h].y * w;
            d.z += bl4[h].z * w; d.w += bl4[h].w * w;
        }
        *(float4*)&sd[g * N_TOK + j] = d;
        float mx = fmaxf(fmaxf(d.x, d.y), fmaxf(d.z, d.w));
        m[g] = mx;
        l[g] = __expf(d.x - mx) + __expf(d.y - mx)
             + __expf(d.z - mx) + __expf(d.w - mx);
    }

#pragma unroll
    for (int g = 0; g < HEADS; g++) {
        for (int o = 16; o > 0; o >>= 1) {
            float m2 = __shfl_xor_sync(0xffffffffu, m[g], o);
            float l2 = __shfl_xor_sync(0xffffffffu, l[g], o);
            float nm = fmaxf(m[g], m2);
            l[g] = l[g] * __expf(m[g] - nm) + l2 * __expf(m2 - nm);
            m[g] = nm;
        }
    }
    int warp = tid >> 5, lane = tid & 31;
    if (lane == 0) {
#pragma unroll
        for (int g = 0; g < HEADS; g++) { redm[warp][g] = m[g]; redl[warp][g] = l[g]; }
    }
    __syncthreads();
    if (tid < HEADS) {
        int g = tid;
        float M = redm[0][g], L = redl[0][g];
#pragma unroll
        for (int w = 1; w < 16; w++) {
            float m2 = redm[w][g], l2 = redl[w][g];
            float nm = fmaxf(M, m2);
            L = L * __expf(M - nm) + l2 * __expf(m2 - nm);
            M = nm;
        }
        fm[g] = M; fl[g] = 1.0f / L;
    }
    __syncthreads();

    float4 p4[HEADS];
#pragma unroll
    for (int h = 0; h < HEADS; h++) {
        float mh = fm[h], li = fl[h];
        float4 d = *(const float4*)&sd[h * N_TOK + j];
        p4[h].x = __expf(d.x - mh) * li;
        p4[h].y = __expf(d.y - mh) * li;
        p4[h].z = __expf(d.z - mh) * li;
        p4[h].w = __expf(d.w - mh) * li;
    }
    const size_t rbase = (size_t)i * (HEADS * N_TOK);
#pragma unroll
    for (int g = 0; g < HEADS; g++) {
        float4 a = make_float4(0.f, 0.f, 0.f, 0.f);
#pragma unroll
        for (int h = 0; h < HEADS; h++) {
            float w = smixB[h * HEADS + g];
            a.x += p4[h].x * w; a.y += p4[h].y * w;
            a.z += p4[h].z * w; a.w += p4[h].w * w;
        }
        fp16 h0, l0, h1, l1;
        size_t o = rbase + g * N_TOK + j;
        split2h(a.x, h0, l0); split2h(a.y, h1, l1);
        ((__half2*)&ath[o])[0] = __halves2half2(h0, h1);
        ((__half2*)&atl[o])[0] = __halves2half2(l0, l1);
        split2h(a.z, h0, l0); split2h(a.w, h1, l1);
        ((__half2*)&ath[o])[1] = __halves2half2(h0, h1);
        ((__half2*)&atl[o])[1] = __halves2half2(l0, l1);
    }
}

// ---------------- launch ----------------
extern "C" void kernel_launch(void* const* d_in, const int* in_sizes, int n_in,
                              void* d_out, int out_size)
{
    const float* x        = (const float*)d_in[0];
    const float* h_in     = (const float*)d_in[1];
    const float* ln_g     = (const float*)d_in[2];
    const float* ln_b     = (const float*)d_in[3];
    const float* Wq       = (const float*)d_in[4];
    const float* Wkv      = (const float*)d_in[5];
    const float* mix_pre  = (const float*)d_in[6];
    const float* mix_post = (const float*)d_in[7];
    const float* Wout     = (const float*)d_in[8];
    const float* bout     = (const float*)d_in[9];

    float* out = (float*)d_out;
    float* blended_out = out + (size_t)N_TOK * DIMX;

    float* c12;
    fp16 *xnh, *xnl, *wqkv, *wo, *qh, *ql, *k, *vt, *ath, *atl, *aoh, *aol;
    cudaGetSymbolAddress((void**)&c12,  g_c12);
    cudaGetSymbolAddress((void**)&xnh,  g_xnh);
    cudaGetSymbolAddress((void**)&xnl,  g_xnl);
    cudaGetSymbolAddress((void**)&wqkv, g_wqkv);
    cudaGetSymbolAddress((void**)&wo,   g_wo);
    cudaGetSymbolAddress((void**)&qh,   g_qh);
    cudaGetSymbolAddress((void**)&ql,   g_ql);
    cudaGetSymbolAddress((void**)&k,    g_k);
    cudaGetSymbolAddress((void**)&vt,   g_vt);
    cudaGetSymbolAddress((void**)&ath,  g_ath);
    cudaGetSymbolAddress((void**)&atl,  g_atl);
    cudaGetSymbolAddress((void**)&aoh,  g_aoh);
    cudaGetSymbolAddress((void**)&aol,  g_aol);

    // per-stage smem (bytes): (2*BM + BN) * 128
    const int SM_BIG  = 2 * (2 * 128 + 128) * 128;   // 98304 (BN=128, 2 stages)
    const int SM_QK   = (2 * 128 + 128) * 128;       // 49152 (KT=1, 1 stage)
    const int SM_AV   = 2 * (2 * 128 + 64) * 128;    // 81920 (BN=64, 2 stages)
    const int SM_SOFT = HEADS * N_TOK * 4;           // 131072
    cudaFuncSetAttribute(gemm_2m<128, 128, 64, 32, 0>,
                         cudaFuncAttributeMaxDynamicSharedMemorySize, SM_BIG);
    cudaFuncSetAttribute(gemm_2m<128, 128, 64, 32, 2>,
                         cudaFuncAttributeMaxDynamicSharedMemorySize, SM_BIG);
    cudaFuncSetAttribute(gemm_2m<128, 64, 32, 32, 1>,
                         cudaFuncAttributeMaxDynamicSharedMemorySize, SM_AV);
    cudaFuncSetAttribute(fused_softmax,
                         cudaFuncAttributeMaxDynamicSharedMemorySize, SM_SOFT);

    // 1. layernorm + fp16 split
    ln_split_kernel<<<N_TOK, 256>>>(x, ln_g, ln_b, xnh, xnl);

    // 2. weight transposes -> single fp16 K-major
    tsingle_kernel<<<dim3(32, 32, 1), 256>>>(Wq, INNER, 0, wqkv, DIMX, 0, DIMX, INNER);
    tsingle_kernel<<<dim3(64, 32, 1), 256>>>(Wkv, 2 * INNER, 0,
                                             wqkv + (size_t)INNER * DIMX, DIMX, 0,
                                             DIMX, 2 * INNER);
    tsingle_kernel<<<dim3(32, 32, 1), 256>>>(Wout, DIMX, 0, wo, INNER, 0, INNER, DIMX);

    // 3. c12 = xn @ [Wq|Wkv]  (M=2048, N=3072, K=1024)
    gemm_2m<128, 128, 64, 32, 0><<<dim3(NQKV / 128, N_TOK / 128, 1), 256, SM_BIG>>>(
        xnh, xnl, wqkv, c12, nullptr, nullptr, nullptr,
        DIMX, DIMX, DIMX, NQKV, 0, 0, 0, 1.f, nullptr);

    // 4. remap q (split) / k (single); 5. v^T (single)
    remap_split<<<(N_TOK * INNER + 255) / 256, 256>>>(c12, qh, ql, k);
    tsingle_kernel<<<dim3(2, 64, HEADS), 256>>>(c12 + 2 * INNER, NQKV, DHEAD,
                                                vt, N_TOK, (long long)DHEAD * N_TOK,
                                                N_TOK, DHEAD);

    // 6. blended[h][i][j] = 0.45*SCALE*(q@k^T) + 0.55*h  (epilogue blend)
    gemm_2m<128, 128, 64, 32, 2><<<dim3(N_TOK / 128, N_TOK / 128, HEADS), 256, SM_QK>>>(
        qh, ql, k, blended_out, nullptr, nullptr, h_in,
        DHEAD, DHEAD, DHEAD, N_TOK,
        (long long)N_TOK * DHEAD, (long long)N_TOK * DHEAD,
        (long long)N_TOK * N_TOK,
        SCALE_C, nullptr);

    // 7. fused mix_pre + softmax + mix_post -> attn fp16 hi/lo [i][g][j]
    fused_softmax<<<N_TOK, 512, SM_SOFT>>>(blended_out, mix_pre, mix_post, ath, atl);

    // 8. ao = attn @ v  (per head; M=2048, N=64, K=2048) -> fp16 hi/lo
    gemm_2m<128, 64, 32, 32, 1><<<dim3(1, N_TOK / 128, HEADS), 256, SM_AV>>>(
        ath, atl, vt, nullptr, aoh, aol, nullptr,
        N_TOK, HEADS * N_TOK, N_TOK, INNER,
        (long long)N_TOK, (long long)DHEAD * N_TOK, (long long)DHEAD,
        1.f, nullptr);

    // 9. out = ao @ Wout + bout  (M=2048, N=1024, K=1024)
    gemm_2m<128, 128, 64, 32, 0><<<dim3(DIMX / 128, N_TOK / 128, 1), 256, SM_BIG>>>(
        aoh, aol, wo, out, nullptr, nullptr, nullptr,
        INNER, INNER, INNER, DIMX, 0, 0, 0, 1.f, bout);

    (void)in_sizes; (void)n_in; (void)out_size;
}